// round 11
// baseline (speedup 1.0000x reference)
#include <cuda_runtime.h>
#include <cuda_fp16.h>
#include <stdint.h>

#define NN   50000
#define EE   800000
#define EMB  384
#define DESK 768

// ---------------- scratch (no allocations allowed) ----------------
__device__ __align__(16) __half g_h[NN * EMB];      // fp16 message rows
__device__ float g_dinv[NN];
__device__ int   g_deg[NN];
__device__ int   g_rowptr[NN + 1];
__device__ int   g_cursor[NN];
__device__ int   g_csr[EE];
__device__ int   g_scan[NN];
__device__ int   g_bsum[256];
__device__ int   g_boff[256];
__device__ int   g_is64;

__device__ __align__(16) __half g_desh[NN * DESK];   // des: single fp16
__device__ __align__(16) __half g_x0h[NN * EMB];
__device__ __align__(16) __half g_x0l[NN * EMB];
__device__ __align__(16) __half g_x1h[NN * EMB];
__device__ __align__(16) __half g_x1l[NN * EMB];

#define WTOT 688128
__device__ __align__(16) __half g_w[WTOT];
enum { WOFF_DES = 0, WOFF_IN = 98304, WOFF_G1 = 245760, WOFF_G2 = 393216, WOFF_O1 = 540672 };

__device__ __forceinline__ float leaky(float v) { return v > 0.0f ? v : 0.01f * v; }

__device__ __forceinline__ void split1h(float v, __half& h, __half& l) {
    h = __float2half_rn(v);
    l = __float2half_rn(v - __half2float(h));
}
__device__ __forceinline__ uint32_t packh(__half a, __half b) {
    __half2 t = __halves2half2(a, b);
    return *(uint32_t*)&t;
}

// ---------------- low-level helpers ----------------
__device__ __forceinline__ uint32_t smem_u32(const void* p) {
    uint32_t a;
    asm("{ .reg .u64 t; cvta.to.shared.u64 t, %1; cvt.u32.u64 %0, t; }" : "=r"(a) : "l"(p));
    return a;
}
__device__ __forceinline__ void cp_async16(uint32_t dst, const void* src) {
    asm volatile("cp.async.cg.shared.global [%0], [%1], 16;" :: "r"(dst), "l"(src));
}
__device__ __forceinline__ void cp_commit() { asm volatile("cp.async.commit_group;" ::: "memory"); }
__device__ __forceinline__ void cp_wait_all() { asm volatile("cp.async.wait_group 0;" ::: "memory"); }
__device__ __forceinline__ void cp_wait_1()  { asm volatile("cp.async.wait_group 1;" ::: "memory"); }

__device__ __forceinline__ void mma16816(float& d0, float& d1, float& d2, float& d3,
                                         uint32_t a0, uint32_t a1, uint32_t a2, uint32_t a3,
                                         uint32_t b0, uint32_t b1)
{
    asm volatile(
        "mma.sync.aligned.m16n8k16.row.col.f32.f16.f16.f32 "
        "{%0,%1,%2,%3}, {%4,%5,%6,%7}, {%8,%9}, {%0,%1,%2,%3};"
        : "+f"(d0), "+f"(d1), "+f"(d2), "+f"(d3)
        : "r"(a0), "r"(a1), "r"(a2), "r"(a3), "r"(b0), "r"(b1));
}
__device__ __forceinline__ void ldsm4(uint32_t& r0, uint32_t& r1, uint32_t& r2, uint32_t& r3,
                                      uint32_t addr)
{
    asm volatile("ldmatrix.sync.aligned.m8n8.x4.shared.b16 {%0,%1,%2,%3}, [%4];"
                 : "=r"(r0), "=r"(r1), "=r"(r2), "=r"(r3) : "r"(addr));
}

// ---------------- fp16(-split) HMMA GEMM: D = (Ah[+Al]) @ B^T ----------------
// K-chunk 64 (128B rows), pitch 144B: 8-row ldmatrix wavefronts rotate 4 words -> conflict-free.
#define ROW_PITCH 144
#define TILE_BYTES (128 * ROW_PITCH)     // 18432

template<bool ASPLIT, bool LEAKY_F, bool BIAS_F, bool SCALE_F, bool WHALF, bool WSPLIT, bool FUSE>
__global__ __launch_bounds__(256) void gemm_hmma(
    const __half* __restrict__ Ah, const __half* __restrict__ Al, int K,
    const __half* __restrict__ B,
    const float* __restrict__ bias,
    __half* __restrict__ Cf, __half* __restrict__ Ch, __half* __restrict__ Cl,
    int ldc, int M,
    const float* __restrict__ Wo2, float* __restrict__ Out)
{
    constexpr int NT = ASPLIT ? 3 : 2;
    constexpr int STAGE = NT * TILE_BYTES;

    extern __shared__ char smem[];
    const uint32_t sb = smem_u32(smem);
    const int tid  = threadIdx.x;
    const int wid  = tid >> 5;
    const int lane = tid & 31;
    const int g    = lane >> 2;
    const int tig  = lane & 3;
    const int warp_m = wid >> 2;
    const int warp_n = wid & 3;
    const int block_row = blockIdx.y * 128;
    const int block_col = blockIdx.x * 128;

    const __half* bases[3];
    bases[0] = Ah; bases[1] = ASPLIT ? Al : B; bases[2] = B;

    float acc[4][4][4];
#pragma unroll
    for (int mt = 0; mt < 4; mt++)
#pragma unroll
        for (int nt = 0; nt < 4; nt++)
#pragma unroll
            for (int q = 0; q < 4; q++) acc[mt][nt][q] = 0.0f;

    const int NC = K >> 6;   // chunks of 64

    // loader: NT tiles x 128 rows x 8 granules = NT*1024 granules / 256 thr
    auto load_stage = [&](int c, int s) {
        const uint32_t stage = sb + s * STAGE;
        const int kbyte = c * 128;   // 64 elems * 2B
#pragma unroll
        for (int i = 0; i < NT * 4; i++) {
            int gi   = tid + i * 256;
            int tile = gi >> 10;            // 0..NT-1
            int r    = (gi >> 3) & 127;
            int c16  = gi & 7;
            int grow;
            if (tile < NT - 1) { grow = block_row + r; if (grow >= M) grow = M - 1; }
            else               { grow = block_col + r; }
            const char* src = (const char*)bases[tile] + (size_t)grow * K * 2 + kbyte + c16 * 16;
            cp_async16(stage + tile * TILE_BYTES + r * ROW_PITCH + c16 * 16, src);
        }
        cp_commit();
    };

    const uint32_t aOff = (uint32_t)(warp_m * 64 + (lane & 15)) * ROW_PITCH + (lane >> 4) * 16;
    const uint32_t bOff = (NT - 1) * TILE_BYTES
                        + (uint32_t)(warp_n * 32 + (lane & 7) + ((lane >> 4) * 8)) * ROW_PITCH
                        + ((lane >> 3) & 1) * 16;

    load_stage(0, 0);

    for (int c = 0; c < NC; c++) {
        if (c + 1 < NC) { load_stage(c + 1, (c + 1) & 1); cp_wait_1(); }
        else            { cp_wait_all(); }
        __syncthreads();

        const uint32_t stage = sb + (c & 1) * STAGE;
        const uint32_t aBase = stage + aOff;
        const uint32_t bBase = stage + bOff;

#pragma unroll
        for (int kk = 0; kk < 64; kk += 16) {
            const uint32_t ko = kk * 2;
            uint32_t af[ASPLIT ? 2 : 1][4][4];
#pragma unroll
            for (int arr = 0; arr < (ASPLIT ? 2 : 1); arr++)
#pragma unroll
                for (int mt = 0; mt < 4; mt++)
                    ldsm4(af[arr][mt][0], af[arr][mt][1], af[arr][mt][2], af[arr][mt][3],
                          aBase + arr * TILE_BYTES + mt * (16 * ROW_PITCH) + ko);

            uint32_t bf[4][2];
#pragma unroll
            for (int p = 0; p < 2; p++)
                ldsm4(bf[2 * p][0], bf[2 * p][1], bf[2 * p + 1][0], bf[2 * p + 1][1],
                      bBase + p * (16 * ROW_PITCH) + ko);

#pragma unroll
            for (int mt = 0; mt < 4; mt++)
#pragma unroll
                for (int nt = 0; nt < 4; nt++) {
                    float* d = acc[mt][nt];
                    mma16816(d[0], d[1], d[2], d[3],
                             af[0][mt][0], af[0][mt][1], af[0][mt][2], af[0][mt][3],
                             bf[nt][0], bf[nt][1]);
                    if (ASPLIT)
                        mma16816(d[0], d[1], d[2], d[3],
                                 af[1][mt][0], af[1][mt][1], af[1][mt][2], af[1][mt][3],
                                 bf[nt][0], bf[nt][1]);
                }
        }
        __syncthreads();
    }

    if (FUSE) {
#pragma unroll
        for (int mt = 0; mt < 4; mt++) {
#pragma unroll
            for (int half = 0; half < 2; half++) {
                int row = block_row + warp_m * 64 + mt * 16 + g + half * 8;
                if (row < M) {
                    float s0 = 0.f, s1 = 0.f;
#pragma unroll
                    for (int nt = 0; nt < 4; nt++) {
                        int col = block_col + warp_n * 32 + nt * 8 + 2 * tig;
                        float v0 = acc[mt][nt][half * 2 + 0] + bias[col];
                        float v1 = acc[mt][nt][half * 2 + 1] + bias[col + 1];
                        v0 = leaky(v0); v1 = leaky(v1);
                        s0 += v0 * Wo2[col * 2 + 0] + v1 * Wo2[(col + 1) * 2 + 0];
                        s1 += v0 * Wo2[col * 2 + 1] + v1 * Wo2[(col + 1) * 2 + 1];
                    }
                    s0 += __shfl_xor_sync(0xffffffffu, s0, 1);
                    s0 += __shfl_xor_sync(0xffffffffu, s0, 2);
                    s1 += __shfl_xor_sync(0xffffffffu, s1, 1);
                    s1 += __shfl_xor_sync(0xffffffffu, s1, 2);
                    if (tig == 0) {
                        atomicAdd(&Out[row * 2 + 0], s0);
                        atomicAdd(&Out[row * 2 + 1], s1);
                    }
                }
            }
        }
    } else {
#pragma unroll
        for (int mt = 0; mt < 4; mt++) {
#pragma unroll
            for (int nt = 0; nt < 4; nt++) {
                int row0 = block_row + warp_m * 64 + mt * 16 + g;
                int row1 = row0 + 8;
                int col  = block_col + warp_n * 32 + nt * 8 + 2 * tig;
                float b0 = 0.f, b1 = 0.f;
                if (BIAS_F) { b0 = bias[col]; b1 = bias[col + 1]; }
#pragma unroll
                for (int half = 0; half < 2; half++) {
                    int row = half ? row1 : row0;
                    if (row < M) {
                        float v0 = acc[mt][nt][half * 2 + 0];
                        float v1 = acc[mt][nt][half * 2 + 1];
                        if (BIAS_F)  { v0 += b0; v1 += b1; }
                        if (LEAKY_F) { v0 = leaky(v0); v1 = leaky(v1); }
                        if (SCALE_F) { float dv = g_dinv[row]; v0 *= dv; v1 *= dv; }
                        size_t off = (size_t)row * ldc + col;
                        if (WHALF) *(__half2*)(Cf + off) = __floats2half2_rn(v0, v1);
                        if (WSPLIT) {
                            __half h0, h1, l0, l1;
                            split1h(v0, h0, l0); split1h(v1, h1, l1);
                            *(uint32_t*)(Ch + off) = packh(h0, h1);
                            *(uint32_t*)(Cl + off) = packh(l0, l1);
                        }
                    }
                }
            }
        }
    }
}

// ---------------- conversions ----------------
__global__ void cvt_f32h(const float* __restrict__ x, __half* __restrict__ o, int n4)
{
    int i = blockIdx.x * blockDim.x + threadIdx.x;
    if (i >= n4) return;
    float4 v = ((const float4*)x)[i];
    uint2 u;
    u.x = packh(__float2half_rn(v.x), __float2half_rn(v.y));
    u.y = packh(__float2half_rn(v.z), __float2half_rn(v.w));
    ((uint2*)o)[i] = u;
}

// W [K, Nn] fp32 -> out [Nn, K] fp16 (transpose)
__global__ void wcvtT(const float* __restrict__ W, int K, int Nn, __half* __restrict__ o)
{
    int idx = blockIdx.x * blockDim.x + threadIdx.x;
    if (idx >= K * Nn) return;
    int k = idx / Nn, n = idx % Nn;
    o[(size_t)n * K + k] = __float2half_rn(W[idx]);
}

// ---------------- small front projections ----------------
__global__ void front_small(const float* __restrict__ nump, const float* __restrict__ catp,
                            const float* __restrict__ Wn, const float* __restrict__ bn,
                            const float* __restrict__ Wc, const float* __restrict__ bc)
{
    int node = blockIdx.x;
    int j = threadIdx.x;
    float n0 = nump[node * 4 + 0], n1 = nump[node * 4 + 1];
    float n2 = nump[node * 4 + 2], n3 = nump[node * 4 + 3];
    float c0 = catp[node * 3 + 0], c1 = catp[node * 3 + 1], c2 = catp[node * 3 + 2];

    float a = bn[j];
    a = fmaf(n0, Wn[0 * 128 + j], a); a = fmaf(n1, Wn[1 * 128 + j], a);
    a = fmaf(n2, Wn[2 * 128 + j], a); a = fmaf(n3, Wn[3 * 128 + j], a);
    float b = bc[j];
    b = fmaf(c0, Wc[0 * 128 + j], b); b = fmaf(c1, Wc[1 * 128 + j], b);
    b = fmaf(c2, Wc[2 * 128 + j], b);

    a = leaky(a); b = leaky(b);
    __half h, l;
    size_t base = (size_t)node * EMB;
    split1h(a, h, l); g_x0h[base + 128 + j] = h; g_x0l[base + 128 + j] = l;
    split1h(b, h, l); g_x0h[base + 256 + j] = h; g_x0l[base + 256 + j] = l;
}

// ---------------- edges / CSR ----------------
__device__ __forceinline__ void load_edge(const void* ei, int e, int& src, int& dst) {
    if (g_is64) {
        const long long* p = (const long long*)ei;
        src = (int)p[e]; dst = (int)p[EE + e];
    } else {
        const int* p = (const int*)ei;
        src = p[e]; dst = p[EE + e];
    }
}
__global__ void detect_idx_dtype(const void* ei) {
    const long long* p = (const long long*)ei;
    int ok64 = 1;
    for (int i = 0; i < 64; i++) {
        long long v = p[i];
        if (v < 0 || v >= NN) { ok64 = 0; break; }
    }
    g_is64 = ok64;
}
__global__ void zero_deg() {
    int i = blockIdx.x * blockDim.x + threadIdx.x;
    if (i < NN) g_deg[i] = 0;
}
__global__ void deg_count(const void* __restrict__ ei) {
    int e = blockIdx.x * blockDim.x + threadIdx.x;
    if (e < EE) { int s, d; load_edge(ei, e, s, d); atomicAdd(&g_deg[d], 1); }
}

#define SCAN_BLKS ((NN + 255) / 256)   // 196
__global__ void scan_phase1() {
    __shared__ int ws[8];
    int i = blockIdx.x * 256 + threadIdx.x;
    int lane = threadIdx.x & 31, wd = threadIdx.x >> 5;
    int v = (i < NN) ? g_deg[i] : 0;
    int s = v;
#pragma unroll
    for (int o = 1; o < 32; o <<= 1) {
        int t = __shfl_up_sync(0xffffffffu, s, o);
        if (lane >= o) s += t;
    }
    if (lane == 31) ws[wd] = s;
    __syncthreads();
    if (wd == 0) {
        int u = (lane < 8) ? ws[lane] : 0;
        int ss = u;
#pragma unroll
        for (int o = 1; o < 8; o <<= 1) {
            int t = __shfl_up_sync(0xffffffffu, ss, o);
            if (lane >= o) ss += t;
        }
        if (lane < 8) ws[lane] = ss;
    }
    __syncthreads();
    int incl = s + (wd ? ws[wd - 1] : 0);
    if (i < NN) g_scan[i] = incl;
    if (threadIdx.x == 255) g_bsum[blockIdx.x] = incl;
}
__global__ void scan_phase2() {
    __shared__ int ws[8];
    int t = threadIdx.x;
    int lane = t & 31, wd = t >> 5;
    int v = (t < SCAN_BLKS) ? g_bsum[t] : 0;
    int s = v;
#pragma unroll
    for (int o = 1; o < 32; o <<= 1) {
        int u = __shfl_up_sync(0xffffffffu, s, o);
        if (lane >= o) s += u;
    }
    if (lane == 31) ws[wd] = s;
    __syncthreads();
    if (wd == 0) {
        int u = (lane < 8) ? ws[lane] : 0;
        int ss = u;
#pragma unroll
        for (int o = 1; o < 8; o <<= 1) {
            int x = __shfl_up_sync(0xffffffffu, ss, o);
            if (lane >= o) ss += x;
        }
        if (lane < 8) ws[lane] = ss;
    }
    __syncthreads();
    int incl = s + (wd ? ws[wd - 1] : 0);
    if (t < SCAN_BLKS) g_boff[t] = incl - v;
}
__global__ void scan_phase3() {
    int i = blockIdx.x * 256 + threadIdx.x;
    if (i >= NN) return;
    int incl = g_scan[i] + g_boff[blockIdx.x];
    int d = g_deg[i];
    int beg = incl - d;
    g_rowptr[i] = beg;
    g_cursor[i] = beg;
    g_dinv[i] = rsqrtf((float)d + 1.0f);
    if (i == NN - 1) g_rowptr[NN] = incl;
}

__global__ void csr_fill(const void* __restrict__ ei) {
    int e = blockIdx.x * blockDim.x + threadIdx.x;
    if (e < EE) {
        int s, d; load_edge(ei, e, s, d);
        int pos = atomicAdd(&g_cursor[d], 1);
        g_csr[pos] = s;
    }
}

// ---------------- fused gather-aggregate: 3 warps per node (128 cols each) ----------------
__global__ __launch_bounds__(256) void gcn_agg(
    const __half* __restrict__ y, const float* __restrict__ bias,
    __half* __restrict__ oh, __half* __restrict__ ol)
{
    int w = (blockIdx.x * blockDim.x + threadIdx.x) >> 5;
    int lane = threadIdx.x & 31;
    if (w >= NN * 3) return;
    int node  = w / 3;
    int chunk = w - node * 3;
    int ci = chunk * 32 + lane;        // uint2 index within row (0..95)
    int beg = g_rowptr[node], end = g_rowptr[node + 1];

    float a0 = 0.f, a1 = 0.f, a2 = 0.f, a3 = 0.f;

    for (int base = beg; base < end; base += 32) {
        int cnt = min(32, end - base);
        int s = (lane < cnt) ? g_csr[base + lane] : 0;
        for (int j = 0; j < cnt; j++) {
            int sj = __shfl_sync(0xffffffffu, s, j);
            uint2 u = ((const uint2*)(y + (size_t)sj * EMB))[ci];
            float2 f0 = __half22float2(*(__half2*)&u.x);
            float2 f1 = __half22float2(*(__half2*)&u.y);
            a0 += f0.x; a1 += f0.y; a2 += f1.x; a3 += f1.y;
        }
    }
    // self term
    {
        uint2 u = ((const uint2*)(y + (size_t)node * EMB))[ci];
        float2 f0 = __half22float2(*(__half2*)&u.x);
        float2 f1 = __half22float2(*(__half2*)&u.y);
        a0 += f0.x; a1 += f0.y; a2 += f1.x; a3 += f1.y;
    }

    float dv = g_dinv[node];
    float4 b = ((const float4*)bias)[ci];
    float r0 = fmaf(dv, a0, b.x);
    float r1 = fmaf(dv, a1, b.y);
    float r2 = fmaf(dv, a2, b.z);
    float r3 = fmaf(dv, a3, b.w);

    __half h0, h1, h2, h3, l0, l1, l2, l3;
    split1h(r0, h0, l0); split1h(r1, h1, l1); split1h(r2, h2, l2); split1h(r3, h3, l3);
    uint2 uh; uh.x = packh(h0, h1); uh.y = packh(h2, h3);
    uint2 ul; ul.x = packh(l0, l1); ul.y = packh(l2, l3);
    ((uint2*)(oh + (size_t)node * EMB))[ci] = uh;
    ((uint2*)(ol + (size_t)node * EMB))[ci] = ul;
}

// ---------------- output init with bias ----------------
__global__ void init_out(float* __restrict__ out, const float* __restrict__ b) {
    int i = blockIdx.x * blockDim.x + threadIdx.x;
    if (i < NN) {
        out[i * 2 + 0] = b[0];
        out[i * 2 + 1] = b[1];
    }
}

// ---------------- host orchestration ----------------
#define SMEM_SPLIT  (2 * 3 * TILE_BYTES)   // 110592
#define SMEM_SINGLE (2 * 2 * TILE_BYTES)   // 73728

extern "C" void kernel_launch(void* const* d_in, const int* in_sizes, int n_in,
                              void* d_out, int out_size)
{
    const float* des  = (const float*)d_in[0];
    const float* nump = (const float*)d_in[2];
    const float* catp = (const float*)d_in[3];
    const void*  ei   = d_in[4];
    const float* W_des = (const float*)d_in[5];  const float* b_des = (const float*)d_in[6];
    const float* W_num = (const float*)d_in[7];  const float* b_num = (const float*)d_in[8];
    const float* W_cat = (const float*)d_in[9];  const float* b_cat = (const float*)d_in[10];
    const float* W_in  = (const float*)d_in[11]; const float* b_in  = (const float*)d_in[12];
    const float* W_g1  = (const float*)d_in[13]; const float* b_g1  = (const float*)d_in[14];
    const float* W_g2  = (const float*)d_in[15]; const float* b_g2  = (const float*)d_in[16];
    const float* W_o1  = (const float*)d_in[17]; const float* b_o1  = (const float*)d_in[18];
    const float* W_o2  = (const float*)d_in[19]; const float* b_o2  = (const float*)d_in[20];
    float* out = (float*)d_out;

    __half *h, *desh, *x0h, *x0l, *x1h, *x1l, *w;
    cudaGetSymbolAddress((void**)&h,    g_h);
    cudaGetSymbolAddress((void**)&desh, g_desh);
    cudaGetSymbolAddress((void**)&x0h,  g_x0h);
    cudaGetSymbolAddress((void**)&x0l,  g_x0l);
    cudaGetSymbolAddress((void**)&x1h,  g_x1h);
    cudaGetSymbolAddress((void**)&x1l,  g_x1l);
    cudaGetSymbolAddress((void**)&w,    g_w);

    cudaFuncSetAttribute(gemm_hmma<false, true, true, false, false, true, false>,
                         cudaFuncAttributeMaxDynamicSharedMemorySize, SMEM_SINGLE);
    cudaFuncSetAttribute(gemm_hmma<true, true, true, false, false, true, false>,
                         cudaFuncAttributeMaxDynamicSharedMemorySize, SMEM_SPLIT);
    cudaFuncSetAttribute(gemm_hmma<true, false, false, true, true, false, false>,
                         cudaFuncAttributeMaxDynamicSharedMemorySize, SMEM_SPLIT);
    cudaFuncSetAttribute(gemm_hmma<true, true, true, false, false, false, true>,
                         cudaFuncAttributeMaxDynamicSharedMemorySize, SMEM_SPLIT);

    const int MB = (NN + 127) / 128;   // 391
    dim3 blk(256);

    // conversions
    cvt_f32h<<<(NN * DESK / 4 + 255) / 256, blk>>>(des, desh, NN * DESK / 4);
    wcvtT<<<(DESK * 128 + 255) / 256, blk>>>(W_des, DESK, 128, w + WOFF_DES);
    wcvtT<<<(EMB * EMB + 255) / 256, blk>>>(W_in, EMB, EMB, w + WOFF_IN);
    wcvtT<<<(EMB * EMB + 255) / 256, blk>>>(W_g1, EMB, EMB, w + WOFF_G1);
    wcvtT<<<(EMB * EMB + 255) / 256, blk>>>(W_g2, EMB, EMB, w + WOFF_G2);
    wcvtT<<<(EMB * EMB + 255) / 256, blk>>>(W_o1, EMB, EMB, w + WOFF_O1);

    // edge preprocessing
    detect_idx_dtype<<<1, 1>>>(ei);
    zero_deg<<<(NN + 255) / 256, blk>>>();
    deg_count<<<(EE + 255) / 256, blk>>>(ei);
    scan_phase1<<<SCAN_BLKS, 256>>>();
    scan_phase2<<<1, 256>>>();
    scan_phase3<<<SCAN_BLKS, 256>>>();
    csr_fill<<<(EE + 255) / 256, blk>>>(ei);

    // des projection -> x0[:, 0:128]  (A single fp16)
    gemm_hmma<false, true, true, false, false, true, false><<<dim3(1, MB), blk, SMEM_SINGLE>>>(
        desh, nullptr, DESK, w + WOFF_DES, b_des,
        nullptr, x0h, x0l, EMB, NN, nullptr, nullptr);
    front_small<<<NN, 128>>>(nump, catp, W_num, b_num, W_cat, b_cat);

    // x1 = leaky(x0 @ W_in + b_in)
    gemm_hmma<true, true, true, false, false, true, false><<<dim3(3, MB), blk, SMEM_SPLIT>>>(
        x0h, x0l, EMB, w + WOFF_IN, b_in,
        nullptr, x1h, x1l, EMB, NN, nullptr, nullptr);

    // ---- GCN conv 1 ----
    gemm_hmma<true, false, false, true, true, false, false><<<dim3(3, MB), blk, SMEM_SPLIT>>>(
        x1h, x1l, EMB, w + WOFF_G1, nullptr,
        h, nullptr, nullptr, EMB, NN, nullptr, nullptr);
    gcn_agg<<<(NN * 3 * 32 + 255) / 256, blk>>>(h, b_g1, x1h, x1l);

    // ---- GCN conv 2 ----
    gemm_hmma<true, false, false, true, true, false, false><<<dim3(3, MB), blk, SMEM_SPLIT>>>(
        x1h, x1l, EMB, w + WOFF_G2, nullptr,
        h, nullptr, nullptr, EMB, NN, nullptr, nullptr);
    gcn_agg<<<(NN * 3 * 32 + 255) / 256, blk>>>(h, b_g2, x1h, x1l);

    // fused: out = leaky(x @ W_o1 + b_o1) @ W_o2 + b_o2
    init_out<<<(NN + 255) / 256, blk>>>(out, b_o2);
    gemm_hmma<true, true, true, false, false, false, true><<<dim3(3, MB), blk, SMEM_SPLIT>>>(
        x1h, x1l, EMB, w + WOFF_O1, b_o1,
        nullptr, nullptr, nullptr, EMB, NN, W_o2, out);
}

// round 13
// speedup vs baseline: 1.1254x; 1.1254x over previous
#include <cuda_runtime.h>
#include <cuda_fp16.h>
#include <stdint.h>

#define NN   50000
#define EE   800000
#define EMB  384
#define DESK 768

// ---------------- scratch (no allocations allowed) ----------------
__device__ __align__(16) __half g_h[NN * EMB];      // fp16 message rows
__device__ float g_dinv[NN];
__device__ int   g_deg[NN];
__device__ int   g_rowptr[NN + 1];
__device__ int   g_cursor[NN];
__device__ int   g_csr[EE];
__device__ int   g_scan[NN];
__device__ int   g_bsum[256];
__device__ int   g_boff[256];
__device__ int   g_is64;

__device__ __align__(16) __half g_desh[NN * DESK];   // des: single fp16
__device__ __align__(16) __half g_x0h[NN * EMB];
__device__ __align__(16) __half g_x0l[NN * EMB];
__device__ __align__(16) __half g_x1h[NN * EMB];
__device__ __align__(16) __half g_x1l[NN * EMB];

#define WTOT 688128
__device__ __align__(16) __half g_w[WTOT];
enum { WOFF_DES = 0, WOFF_IN = 98304, WOFF_G1 = 245760, WOFF_G2 = 393216, WOFF_O1 = 540672 };

__device__ __forceinline__ float leaky(float v) { return v > 0.0f ? v : 0.01f * v; }

__device__ __forceinline__ void split1h(float v, __half& h, __half& l) {
    h = __float2half_rn(v);
    l = __float2half_rn(v - __half2float(h));
}
__device__ __forceinline__ uint32_t packh(__half a, __half b) {
    __half2 t = __halves2half2(a, b);
    return *(uint32_t*)&t;
}

// ---------------- low-level helpers ----------------
__device__ __forceinline__ uint32_t smem_u32(const void* p) {
    uint32_t a;
    asm("{ .reg .u64 t; cvta.to.shared.u64 t, %1; cvt.u32.u64 %0, t; }" : "=r"(a) : "l"(p));
    return a;
}
__device__ __forceinline__ void cp_async16(uint32_t dst, const void* src) {
    asm volatile("cp.async.cg.shared.global [%0], [%1], 16;" :: "r"(dst), "l"(src));
}
__device__ __forceinline__ void cp_commit() { asm volatile("cp.async.commit_group;" ::: "memory"); }
__device__ __forceinline__ void cp_wait_all() { asm volatile("cp.async.wait_group 0;" ::: "memory"); }
__device__ __forceinline__ void cp_wait_1()  { asm volatile("cp.async.wait_group 1;" ::: "memory"); }

__device__ __forceinline__ void mma16816(float& d0, float& d1, float& d2, float& d3,
                                         uint32_t a0, uint32_t a1, uint32_t a2, uint32_t a3,
                                         uint32_t b0, uint32_t b1)
{
    asm volatile(
        "mma.sync.aligned.m16n8k16.row.col.f32.f16.f16.f32 "
        "{%0,%1,%2,%3}, {%4,%5,%6,%7}, {%8,%9}, {%0,%1,%2,%3};"
        : "+f"(d0), "+f"(d1), "+f"(d2), "+f"(d3)
        : "r"(a0), "r"(a1), "r"(a2), "r"(a3), "r"(b0), "r"(b1));
}
__device__ __forceinline__ void ldsm4(uint32_t& r0, uint32_t& r1, uint32_t& r2, uint32_t& r3,
                                      uint32_t addr)
{
    asm volatile("ldmatrix.sync.aligned.m8n8.x4.shared.b16 {%0,%1,%2,%3}, [%4];"
                 : "=r"(r0), "=r"(r1), "=r"(r2), "=r"(r3) : "r"(addr));
}

// ---------------- fp16(-split) HMMA GEMM: D = (Ah[+Al]) @ B^T ----------------
// R10 geometry: K-chunk 32, pitch 80B.
#define ROW_PITCH 80
#define TILE_B    (128 * ROW_PITCH)      // 10240

template<bool ASPLIT, bool LEAKY_F, bool BIAS_F, bool SCALE_F, bool WHALF, bool WSPLIT, bool FUSE>
__global__ __launch_bounds__(256) void gemm_hmma(
    const __half* __restrict__ Ah, const __half* __restrict__ Al, int K,
    const __half* __restrict__ B,
    const float* __restrict__ bias,
    __half* __restrict__ Cf, __half* __restrict__ Ch, __half* __restrict__ Cl,
    int ldc, int M,
    const float* __restrict__ Wo2, float* __restrict__ Out)
{
    constexpr int NT = ASPLIT ? 3 : 2;
    constexpr int STAGE = NT * TILE_B;

    extern __shared__ char smem[];
    const uint32_t sb = smem_u32(smem);
    const int tid  = threadIdx.x;
    const int wid  = tid >> 5;
    const int lane = tid & 31;
    const int g    = lane >> 2;
    const int tig  = lane & 3;
    const int warp_m = wid >> 2;
    const int warp_n = wid & 3;
    const int block_row = blockIdx.y * 128;
    const int block_col = blockIdx.x * 128;

    const __half* bases[3];
    bases[0] = Ah; bases[1] = ASPLIT ? Al : B; bases[2] = B;

    float acc[4][4][4];
#pragma unroll
    for (int mt = 0; mt < 4; mt++)
#pragma unroll
        for (int nt = 0; nt < 4; nt++)
#pragma unroll
            for (int q = 0; q < 4; q++) acc[mt][nt][q] = 0.0f;

    const int NC = K >> 5;   // chunks of 32

    // loader: NT tiles x 128 rows x 4 granules = NT*512 granules / 256 thr
    auto load_stage = [&](int c, int s) {
        const uint32_t stage = sb + s * STAGE;
        const int kbyte = c * 64;   // 32 elems * 2B
#pragma unroll
        for (int i = 0; i < NT * 2; i++) {
            int gi   = tid + i * 256;
            int tile = gi >> 9;            // 0..NT-1
            int r    = (gi >> 2) & 127;
            int c16  = gi & 3;
            int grow;
            if (tile < NT - 1) { grow = block_row + r; if (grow >= M) grow = M - 1; }
            else               { grow = block_col + r; }
            const char* src = (const char*)bases[tile] + (size_t)grow * K * 2 + kbyte + c16 * 16;
            cp_async16(stage + tile * TILE_B + r * ROW_PITCH + c16 * 16, src);
        }
        cp_commit();
    };

    const uint32_t aOff = (uint32_t)(warp_m * 64 + (lane & 15)) * ROW_PITCH + (lane >> 4) * 16;
    const uint32_t bOff = (NT - 1) * TILE_B
                        + (uint32_t)(warp_n * 32 + (lane & 7) + ((lane >> 4) * 8)) * ROW_PITCH
                        + ((lane >> 3) & 1) * 16;

    load_stage(0, 0);

    for (int c = 0; c < NC; c++) {
        if (c + 1 < NC) { load_stage(c + 1, (c + 1) & 1); cp_wait_1(); }
        else            { cp_wait_all(); }
        __syncthreads();

        const uint32_t stage = sb + (c & 1) * STAGE;
        const uint32_t aBase = stage + aOff;
        const uint32_t bBase = stage + bOff;

#pragma unroll
        for (int kk = 0; kk < 32; kk += 16) {
            const uint32_t ko = kk * 2;
            uint32_t af[ASPLIT ? 2 : 1][4][4];
#pragma unroll
            for (int arr = 0; arr < (ASPLIT ? 2 : 1); arr++)
#pragma unroll
                for (int mt = 0; mt < 4; mt++)
                    ldsm4(af[arr][mt][0], af[arr][mt][1], af[arr][mt][2], af[arr][mt][3],
                          aBase + arr * TILE_B + mt * (16 * ROW_PITCH) + ko);

            uint32_t bf[4][2];
#pragma unroll
            for (int p = 0; p < 2; p++)
                ldsm4(bf[2 * p][0], bf[2 * p][1], bf[2 * p + 1][0], bf[2 * p + 1][1],
                      bBase + p * (16 * ROW_PITCH) + ko);

#pragma unroll
            for (int mt = 0; mt < 4; mt++)
#pragma unroll
                for (int nt = 0; nt < 4; nt++) {
                    float* d = acc[mt][nt];
                    mma16816(d[0], d[1], d[2], d[3],
                             af[0][mt][0], af[0][mt][1], af[0][mt][2], af[0][mt][3],
                             bf[nt][0], bf[nt][1]);
                    if (ASPLIT)
                        mma16816(d[0], d[1], d[2], d[3],
                                 af[1][mt][0], af[1][mt][1], af[1][mt][2], af[1][mt][3],
                                 bf[nt][0], bf[nt][1]);
                }
        }
        __syncthreads();
    }

    if (FUSE) {
#pragma unroll
        for (int mt = 0; mt < 4; mt++) {
#pragma unroll
            for (int half = 0; half < 2; half++) {
                int row = block_row + warp_m * 64 + mt * 16 + g + half * 8;
                if (row < M) {
                    float s0 = 0.f, s1 = 0.f;
#pragma unroll
                    for (int nt = 0; nt < 4; nt++) {
                        int col = block_col + warp_n * 32 + nt * 8 + 2 * tig;
                        float v0 = acc[mt][nt][half * 2 + 0] + bias[col];
                        float v1 = acc[mt][nt][half * 2 + 1] + bias[col + 1];
                        v0 = leaky(v0); v1 = leaky(v1);
                        s0 += v0 * Wo2[col * 2 + 0] + v1 * Wo2[(col + 1) * 2 + 0];
                        s1 += v0 * Wo2[col * 2 + 1] + v1 * Wo2[(col + 1) * 2 + 1];
                    }
                    s0 += __shfl_xor_sync(0xffffffffu, s0, 1);
                    s0 += __shfl_xor_sync(0xffffffffu, s0, 2);
                    s1 += __shfl_xor_sync(0xffffffffu, s1, 1);
                    s1 += __shfl_xor_sync(0xffffffffu, s1, 2);
                    if (tig == 0) {
                        atomicAdd(&Out[row * 2 + 0], s0);
                        atomicAdd(&Out[row * 2 + 1], s1);
                    }
                }
            }
        }
    } else {
#pragma unroll
        for (int mt = 0; mt < 4; mt++) {
#pragma unroll
            for (int nt = 0; nt < 4; nt++) {
                int row0 = block_row + warp_m * 64 + mt * 16 + g;
                int row1 = row0 + 8;
                int col  = block_col + warp_n * 32 + nt * 8 + 2 * tig;
                float b0 = 0.f, b1 = 0.f;
                if (BIAS_F) { b0 = bias[col]; b1 = bias[col + 1]; }
#pragma unroll
                for (int half = 0; half < 2; half++) {
                    int row = half ? row1 : row0;
                    if (row < M) {
                        float v0 = acc[mt][nt][half * 2 + 0];
                        float v1 = acc[mt][nt][half * 2 + 1];
                        if (BIAS_F)  { v0 += b0; v1 += b1; }
                        if (LEAKY_F) { v0 = leaky(v0); v1 = leaky(v1); }
                        if (SCALE_F) { float dv = g_dinv[row]; v0 *= dv; v1 *= dv; }
                        size_t off = (size_t)row * ldc + col;
                        if (WHALF) *(__half2*)(Cf + off) = __floats2half2_rn(v0, v1);
                        if (WSPLIT) {
                            __half h0, h1, l0, l1;
                            split1h(v0, h0, l0); split1h(v1, h1, l1);
                            *(uint32_t*)(Ch + off) = packh(h0, h1);
                            *(uint32_t*)(Cl + off) = packh(l0, l1);
                        }
                    }
                }
            }
        }
    }
}

// ---------------- conversions ----------------
__global__ void cvt_f32h(const float* __restrict__ x, __half* __restrict__ o, int n4)
{
    int i = blockIdx.x * blockDim.x + threadIdx.x;
    if (i >= n4) return;
    float4 v = ((const float4*)x)[i];
    uint2 u;
    u.x = packh(__float2half_rn(v.x), __float2half_rn(v.y));
    u.y = packh(__float2half_rn(v.z), __float2half_rn(v.w));
    ((uint2*)o)[i] = u;
}

// W [K, Nn] fp32 -> out [Nn, K] fp16 (transpose)
__global__ void wcvtT(const float* __restrict__ W, int K, int Nn, __half* __restrict__ o)
{
    int idx = blockIdx.x * blockDim.x + threadIdx.x;
    if (idx >= K * Nn) return;
    int k = idx / Nn, n = idx % Nn;
    o[(size_t)n * K + k] = __float2half_rn(W[idx]);
}

// ---------------- small front projections ----------------
__global__ void front_small(const float* __restrict__ nump, const float* __restrict__ catp,
                            const float* __restrict__ Wn, const float* __restrict__ bn,
                            const float* __restrict__ Wc, const float* __restrict__ bc)
{
    int node = blockIdx.x;
    int j = threadIdx.x;
    float n0 = nump[node * 4 + 0], n1 = nump[node * 4 + 1];
    float n2 = nump[node * 4 + 2], n3 = nump[node * 4 + 3];
    float c0 = catp[node * 3 + 0], c1 = catp[node * 3 + 1], c2 = catp[node * 3 + 2];

    float a = bn[j];
    a = fmaf(n0, Wn[0 * 128 + j], a); a = fmaf(n1, Wn[1 * 128 + j], a);
    a = fmaf(n2, Wn[2 * 128 + j], a); a = fmaf(n3, Wn[3 * 128 + j], a);
    float b = bc[j];
    b = fmaf(c0, Wc[0 * 128 + j], b); b = fmaf(c1, Wc[1 * 128 + j], b);
    b = fmaf(c2, Wc[2 * 128 + j], b);

    a = leaky(a); b = leaky(b);
    __half h, l;
    size_t base = (size_t)node * EMB;
    split1h(a, h, l); g_x0h[base + 128 + j] = h; g_x0l[base + 128 + j] = l;
    split1h(b, h, l); g_x0h[base + 256 + j] = h; g_x0l[base + 256 + j] = l;
}

// ---------------- edges / CSR ----------------
__device__ __forceinline__ void load_edge(const void* ei, int e, int& src, int& dst) {
    if (g_is64) {
        const long long* p = (const long long*)ei;
        src = (int)p[e]; dst = (int)p[EE + e];
    } else {
        const int* p = (const int*)ei;
        src = p[e]; dst = p[EE + e];
    }
}
__global__ void detect_idx_dtype(const void* ei) {
    const long long* p = (const long long*)ei;
    int ok64 = 1;
    for (int i = 0; i < 64; i++) {
        long long v = p[i];
        if (v < 0 || v >= NN) { ok64 = 0; break; }
    }
    g_is64 = ok64;
}
__global__ void zero_deg() {
    int i = blockIdx.x * blockDim.x + threadIdx.x;
    if (i < NN) g_deg[i] = 0;
}
__global__ void deg_count(const void* __restrict__ ei) {
    int e = blockIdx.x * blockDim.x + threadIdx.x;
    if (e < EE) { int s, d; load_edge(ei, e, s, d); atomicAdd(&g_deg[d], 1); }
}

#define SCAN_BLKS ((NN + 255) / 256)   // 196
__global__ void scan_phase1() {
    __shared__ int ws[8];
    int i = blockIdx.x * 256 + threadIdx.x;
    int lane = threadIdx.x & 31, wd = threadIdx.x >> 5;
    int v = (i < NN) ? g_deg[i] : 0;
    int s = v;
#pragma unroll
    for (int o = 1; o < 32; o <<= 1) {
        int t = __shfl_up_sync(0xffffffffu, s, o);
        if (lane >= o) s += t;
    }
    if (lane == 31) ws[wd] = s;
    __syncthreads();
    if (wd == 0) {
        int u = (lane < 8) ? ws[lane] : 0;
        int ss = u;
#pragma unroll
        for (int o = 1; o < 8; o <<= 1) {
            int t = __shfl_up_sync(0xffffffffu, ss, o);
            if (lane >= o) ss += t;
        }
        if (lane < 8) ws[lane] = ss;
    }
    __syncthreads();
    int incl = s + (wd ? ws[wd - 1] : 0);
    if (i < NN) g_scan[i] = incl;
    if (threadIdx.x == 255) g_bsum[blockIdx.x] = incl;
}
__global__ void scan_phase2() {
    __shared__ int ws[8];
    int t = threadIdx.x;
    int lane = t & 31, wd = t >> 5;
    int v = (t < SCAN_BLKS) ? g_bsum[t] : 0;
    int s = v;
#pragma unroll
    for (int o = 1; o < 32; o <<= 1) {
        int u = __shfl_up_sync(0xffffffffu, s, o);
        if (lane >= o) s += u;
    }
    if (lane == 31) ws[wd] = s;
    __syncthreads();
    if (wd == 0) {
        int u = (lane < 8) ? ws[lane] : 0;
        int ss = u;
#pragma unroll
        for (int o = 1; o < 8; o <<= 1) {
            int x = __shfl_up_sync(0xffffffffu, ss, o);
            if (lane >= o) ss += x;
        }
        if (lane < 8) ws[lane] = ss;
    }
    __syncthreads();
    int incl = s + (wd ? ws[wd - 1] : 0);
    if (t < SCAN_BLKS) g_boff[t] = incl - v;
}
__global__ void scan_phase3() {
    int i = blockIdx.x * 256 + threadIdx.x;
    if (i >= NN) return;
    int incl = g_scan[i] + g_boff[blockIdx.x];
    int d = g_deg[i];
    int beg = incl - d;
    g_rowptr[i] = beg;
    g_cursor[i] = beg;
    g_dinv[i] = rsqrtf((float)d + 1.0f);
    if (i == NN - 1) g_rowptr[NN] = incl;
}

__global__ void csr_fill(const void* __restrict__ ei) {
    int e = blockIdx.x * blockDim.x + threadIdx.x;
    if (e < EE) {
        int s, d; load_edge(ei, e, s, d);
        int pos = atomicAdd(&g_cursor[d], 1);
        g_csr[pos] = s;
    }
}

// ---------------- fused gather-aggregate (R10 geometry: 1 warp/node) ----------------
__global__ __launch_bounds__(256) void gcn_agg(
    const __half* __restrict__ y, const float* __restrict__ bias,
    __half* __restrict__ oh, __half* __restrict__ ol)
{
    int warp = (blockIdx.x * blockDim.x + threadIdx.x) >> 5;
    int lane = threadIdx.x & 31;
    if (warp >= NN) return;
    int beg = g_rowptr[warp], end = g_rowptr[warp + 1];

    float acc[12];
#pragma unroll
    for (int q = 0; q < 12; q++) acc[q] = 0.0f;

    for (int base = beg; base < end; base += 32) {
        int cnt = min(32, end - base);
        int s = (lane < cnt) ? g_csr[base + lane] : 0;
        for (int j = 0; j < cnt; j++) {
            int sj = __shfl_sync(0xffffffffu, s, j);
            const uint2* ys = (const uint2*)(y + (size_t)sj * EMB);
#pragma unroll
            for (int q = 0; q < 3; q++) {
                uint2 u = ys[lane + q * 32];
                float2 f0 = __half22float2(*(__half2*)&u.x);
                float2 f1 = __half22float2(*(__half2*)&u.y);
                acc[q * 4 + 0] += f0.x; acc[q * 4 + 1] += f0.y;
                acc[q * 4 + 2] += f1.x; acc[q * 4 + 3] += f1.y;
            }
        }
    }
    // self term
    {
        const uint2* yn = (const uint2*)(y + (size_t)warp * EMB);
#pragma unroll
        for (int q = 0; q < 3; q++) {
            uint2 u = yn[lane + q * 32];
            float2 f0 = __half22float2(*(__half2*)&u.x);
            float2 f1 = __half22float2(*(__half2*)&u.y);
            acc[q * 4 + 0] += f0.x; acc[q * 4 + 1] += f0.y;
            acc[q * 4 + 2] += f1.x; acc[q * 4 + 3] += f1.y;
        }
    }

    float dv = g_dinv[warp];
    const float4* bv = (const float4*)bias;
    uint2* ohp = (uint2*)(oh + (size_t)warp * EMB);
    uint2* olp = (uint2*)(ol + (size_t)warp * EMB);
#pragma unroll
    for (int q = 0; q < 3; q++) {
        float4 b = bv[lane + q * 32];
        float r0 = fmaf(dv, acc[q * 4 + 0], b.x);
        float r1 = fmaf(dv, acc[q * 4 + 1], b.y);
        float r2 = fmaf(dv, acc[q * 4 + 2], b.z);
        float r3 = fmaf(dv, acc[q * 4 + 3], b.w);
        __half h0, h1, h2, h3, l0, l1, l2, l3;
        split1h(r0, h0, l0); split1h(r1, h1, l1); split1h(r2, h2, l2); split1h(r3, h3, l3);
        uint2 uh; uh.x = packh(h0, h1); uh.y = packh(h2, h3);
        uint2 ul; ul.x = packh(l0, l1); ul.y = packh(l2, l3);
        ohp[lane + q * 32] = uh;
        olp[lane + q * 32] = ul;
    }
}

// ---------------- output init with bias ----------------
__global__ void init_out(float* __restrict__ out, const float* __restrict__ b) {
    int i = blockIdx.x * blockDim.x + threadIdx.x;
    if (i < NN) {
        out[i * 2 + 0] = b[0];
        out[i * 2 + 1] = b[1];
    }
}

// ---------------- host orchestration ----------------
#define SMEM_SPLIT  (2 * 3 * TILE_B)   // 61440
#define SMEM_SINGLE (2 * 2 * TILE_B)   // 40960

extern "C" void kernel_launch(void* const* d_in, const int* in_sizes, int n_in,
                              void* d_out, int out_size)
{
    const float* des  = (const float*)d_in[0];
    const float* nump = (const float*)d_in[2];
    const float* catp = (const float*)d_in[3];
    const void*  ei   = d_in[4];
    const float* W_des = (const float*)d_in[5];  const float* b_des = (const float*)d_in[6];
    const float* W_num = (const float*)d_in[7];  const float* b_num = (const float*)d_in[8];
    const float* W_cat = (const float*)d_in[9];  const float* b_cat = (const float*)d_in[10];
    const float* W_in  = (const float*)d_in[11]; const float* b_in  = (const float*)d_in[12];
    const float* W_g1  = (const float*)d_in[13]; const float* b_g1  = (const float*)d_in[14];
    const float* W_g2  = (const float*)d_in[15]; const float* b_g2  = (const float*)d_in[16];
    const float* W_o1  = (const float*)d_in[17]; const float* b_o1  = (const float*)d_in[18];
    const float* W_o2  = (const float*)d_in[19]; const float* b_o2  = (const float*)d_in[20];
    float* out = (float*)d_out;

    __half *h, *desh, *x0h, *x0l, *x1h, *x1l, *w;
    cudaGetSymbolAddress((void**)&h,    g_h);
    cudaGetSymbolAddress((void**)&desh, g_desh);
    cudaGetSymbolAddress((void**)&x0h,  g_x0h);
    cudaGetSymbolAddress((void**)&x0l,  g_x0l);
    cudaGetSymbolAddress((void**)&x1h,  g_x1h);
    cudaGetSymbolAddress((void**)&x1l,  g_x1l);
    cudaGetSymbolAddress((void**)&w,    g_w);

    cudaFuncSetAttribute(gemm_hmma<false, true, true, false, false, true, false>,
                         cudaFuncAttributeMaxDynamicSharedMemorySize, SMEM_SINGLE);
    cudaFuncSetAttribute(gemm_hmma<true, true, true, false, false, true, false>,
                         cudaFuncAttributeMaxDynamicSharedMemorySize, SMEM_SPLIT);
    cudaFuncSetAttribute(gemm_hmma<true, false, false, true, true, false, false>,
                         cudaFuncAttributeMaxDynamicSharedMemorySize, SMEM_SPLIT);
    cudaFuncSetAttribute(gemm_hmma<true, true, true, false, false, false, true>,
                         cudaFuncAttributeMaxDynamicSharedMemorySize, SMEM_SPLIT);

    const int MB = (NN + 127) / 128;   // 391
    dim3 blk(256);

    // conversions
    cvt_f32h<<<(NN * DESK / 4 + 255) / 256, blk>>>(des, desh, NN * DESK / 4);
    wcvtT<<<(DESK * 128 + 255) / 256, blk>>>(W_des, DESK, 128, w + WOFF_DES);
    wcvtT<<<(EMB * EMB + 255) / 256, blk>>>(W_in, EMB, EMB, w + WOFF_IN);
    wcvtT<<<(EMB * EMB + 255) / 256, blk>>>(W_g1, EMB, EMB, w + WOFF_G1);
    wcvtT<<<(EMB * EMB + 255) / 256, blk>>>(W_g2, EMB, EMB, w + WOFF_G2);
    wcvtT<<<(EMB * EMB + 255) / 256, blk>>>(W_o1, EMB, EMB, w + WOFF_O1);

    // edge preprocessing
    detect_idx_dtype<<<1, 1>>>(ei);
    zero_deg<<<(NN + 255) / 256, blk>>>();
    deg_count<<<(EE + 255) / 256, blk>>>(ei);
    scan_phase1<<<SCAN_BLKS, 256>>>();
    scan_phase2<<<1, 256>>>();
    scan_phase3<<<SCAN_BLKS, 256>>>();
    csr_fill<<<(EE + 255) / 256, blk>>>(ei);

    // des projection -> x0[:, 0:128]  (A single fp16, 1 MMA/frag)
    gemm_hmma<false, true, true, false, false, true, false><<<dim3(1, MB), blk, SMEM_SINGLE>>>(
        desh, nullptr, DESK, w + WOFF_DES, b_des,
        nullptr, x0h, x0l, EMB, NN, nullptr, nullptr);
    front_small<<<NN, 128>>>(nump, catp, W_num, b_num, W_cat, b_cat);

    // x1 = leaky(x0 @ W_in + b_in)
    gemm_hmma<true, true, true, false, false, true, false><<<dim3(3, MB), blk, SMEM_SPLIT>>>(
        x0h, x0l, EMB, w + WOFF_IN, b_in,
        nullptr, x1h, x1l, EMB, NN, nullptr, nullptr);

    // ---- GCN conv 1 ----
    gemm_hmma<true, false, false, true, true, false, false><<<dim3(3, MB), blk, SMEM_SPLIT>>>(
        x1h, x1l, EMB, w + WOFF_G1, nullptr,
        h, nullptr, nullptr, EMB, NN, nullptr, nullptr);
    gcn_agg<<<(NN * 32 + 255) / 256, blk>>>(h, b_g1, x1h, x1l);

    // ---- GCN conv 2 ----
    gemm_hmma<true, false, false, true, true, false, false><<<dim3(3, MB), blk, SMEM_SPLIT>>>(
        x1h, x1l, EMB, w + WOFF_G2, nullptr,
        h, nullptr, nullptr, EMB, NN, nullptr, nullptr);
    gcn_agg<<<(NN * 32 + 255) / 256, blk>>>(h, b_g2, x1h, x1l);

    // fused: out = leaky(x @ W_o1 + b_o1) @ W_o2 + b_o2
    init_out<<<(NN + 255) / 256, blk>>>(out, b_o2);
    gemm_hmma<true, true, true, false, false, false, true><<<dim3(3, MB), blk, SMEM_SPLIT>>>(
        x1h, x1l, EMB, w + WOFF_O1, b_o1,
        nullptr, nullptr, nullptr, EMB, NN, W_o2, out);
}

// round 15
// speedup vs baseline: 1.4345x; 1.2747x over previous
#include <cuda_runtime.h>
#include <cuda_fp16.h>
#include <stdint.h>

#define NN   50000
#define EE   800000
#define EMB  384
#define DESK 768

// ---------------- scratch (no allocations allowed) ----------------
__device__ __align__(16) __half g_h[NN * EMB];      // fp16 message rows
__device__ float g_dinv[NN];
__device__ int   g_deg[NN];
__device__ int   g_rowptr[NN + 1];
__device__ int   g_cursor[NN];
__device__ int   g_csr[EE];
__device__ int   g_scan[NN];
__device__ int   g_bsum[256];
__device__ int   g_boff[256];
__device__ int   g_is64;

__device__ __align__(16) __half g_desh[NN * DESK];   // des fp16
__device__ __align__(16) __half g_x0[NN * EMB];      // activations: single fp16
__device__ __align__(16) __half g_x1[NN * EMB];

#define WTOT 688128
__device__ __align__(16) __half g_w[WTOT];
enum { WOFF_DES = 0, WOFF_IN = 98304, WOFF_G1 = 245760, WOFF_G2 = 393216, WOFF_O1 = 540672 };

__device__ __forceinline__ float leaky(float v) { return v > 0.0f ? v : 0.01f * v; }
__device__ __forceinline__ uint32_t packh(__half a, __half b) {
    __half2 t = __halves2half2(a, b);
    return *(uint32_t*)&t;
}

// ---------------- low-level helpers ----------------
__device__ __forceinline__ uint32_t smem_u32(const void* p) {
    uint32_t a;
    asm("{ .reg .u64 t; cvta.to.shared.u64 t, %1; cvt.u32.u64 %0, t; }" : "=r"(a) : "l"(p));
    return a;
}
__device__ __forceinline__ void cp_async16(uint32_t dst, const void* src) {
    asm volatile("cp.async.cg.shared.global [%0], [%1], 16;" :: "r"(dst), "l"(src));
}
__device__ __forceinline__ void cp_commit() { asm volatile("cp.async.commit_group;" ::: "memory"); }
__device__ __forceinline__ void cp_wait_all() { asm volatile("cp.async.wait_group 0;" ::: "memory"); }
__device__ __forceinline__ void cp_wait_1()  { asm volatile("cp.async.wait_group 1;" ::: "memory"); }

__device__ __forceinline__ void mma16816(float& d0, float& d1, float& d2, float& d3,
                                         uint32_t a0, uint32_t a1, uint32_t a2, uint32_t a3,
                                         uint32_t b0, uint32_t b1)
{
    asm volatile(
        "mma.sync.aligned.m16n8k16.row.col.f32.f16.f16.f32 "
        "{%0,%1,%2,%3}, {%4,%5,%6,%7}, {%8,%9}, {%0,%1,%2,%3};"
        : "+f"(d0), "+f"(d1), "+f"(d2), "+f"(d3)
        : "r"(a0), "r"(a1), "r"(a2), "r"(a3), "r"(b0), "r"(b1));
}
__device__ __forceinline__ void ldsm4(uint32_t& r0, uint32_t& r1, uint32_t& r2, uint32_t& r3,
                                      uint32_t addr)
{
    asm volatile("ldmatrix.sync.aligned.m8n8.x4.shared.b16 {%0,%1,%2,%3}, [%4];"
                 : "=r"(r0), "=r"(r1), "=r"(r2), "=r"(r3) : "r"(addr));
}

// ---------------- single-fp16 HMMA GEMM: D = A @ B^T ----------------
// K-chunk 32, pitch 80B (R13-validated geometry), 2 tiles/stage.
#define ROW_PITCH 80
#define TILE_B    (128 * ROW_PITCH)      // 10240
#define STAGE     (2 * TILE_B)           // 20480
#define GEMM_SMEM (2 * STAGE)            // 40960

template<bool LEAKY_F, bool BIAS_F, bool SCALE_F, bool FUSE>
__global__ __launch_bounds__(256) void gemm_hmma(
    const __half* __restrict__ A, int K,
    const __half* __restrict__ B,
    const float* __restrict__ bias,
    __half* __restrict__ C, int ldc, int M,
    const float* __restrict__ Wo2, float* __restrict__ Out)
{
    extern __shared__ char smem[];
    const uint32_t sb = smem_u32(smem);
    const int tid  = threadIdx.x;
    const int wid  = tid >> 5;
    const int lane = tid & 31;
    const int g    = lane >> 2;
    const int tig  = lane & 3;
    const int warp_m = wid >> 2;
    const int warp_n = wid & 3;
    const int block_row = blockIdx.y * 128;
    const int block_col = blockIdx.x * 128;

    float acc[4][4][4];
#pragma unroll
    for (int mt = 0; mt < 4; mt++)
#pragma unroll
        for (int nt = 0; nt < 4; nt++)
#pragma unroll
            for (int q = 0; q < 4; q++) acc[mt][nt][q] = 0.0f;

    const int NC = K >> 5;   // chunks of 32

    // loader: 2 tiles x 128 rows x 4 granules = 1024 granules / 256 thr = 4 each
    auto load_stage = [&](int c, int s) {
        const uint32_t stage = sb + s * STAGE;
        const int kbyte = c * 64;
#pragma unroll
        for (int i = 0; i < 4; i++) {
            int gi   = tid + i * 256;
            int tile = gi >> 9;            // 0..1
            int r    = (gi >> 2) & 127;
            int c16  = gi & 3;
            int grow;
            if (tile == 0) { grow = block_row + r; if (grow >= M) grow = M - 1; }
            else           { grow = block_col + r; }
            const __half* base = tile ? B : A;
            const char* src = (const char*)base + (size_t)grow * K * 2 + kbyte + c16 * 16;
            cp_async16(stage + tile * TILE_B + r * ROW_PITCH + c16 * 16, src);
        }
        cp_commit();
    };

    const uint32_t aOff = (uint32_t)(warp_m * 64 + (lane & 15)) * ROW_PITCH + (lane >> 4) * 16;
    const uint32_t bOff = TILE_B
                        + (uint32_t)(warp_n * 32 + (lane & 7) + ((lane >> 4) * 8)) * ROW_PITCH
                        + ((lane >> 3) & 1) * 16;

    load_stage(0, 0);

    for (int c = 0; c < NC; c++) {
        if (c + 1 < NC) { load_stage(c + 1, (c + 1) & 1); cp_wait_1(); }
        else            { cp_wait_all(); }
        __syncthreads();

        const uint32_t stage = sb + (c & 1) * STAGE;
        const uint32_t aBase = stage + aOff;
        const uint32_t bBase = stage + bOff;

#pragma unroll
        for (int kk = 0; kk < 32; kk += 16) {
            const uint32_t ko = kk * 2;
            uint32_t af[4][4];
#pragma unroll
            for (int mt = 0; mt < 4; mt++)
                ldsm4(af[mt][0], af[mt][1], af[mt][2], af[mt][3],
                      aBase + mt * (16 * ROW_PITCH) + ko);

            uint32_t bf[4][2];
#pragma unroll
            for (int p = 0; p < 2; p++)
                ldsm4(bf[2 * p][0], bf[2 * p][1], bf[2 * p + 1][0], bf[2 * p + 1][1],
                      bBase + p * (16 * ROW_PITCH) + ko);

#pragma unroll
            for (int mt = 0; mt < 4; mt++)
#pragma unroll
                for (int nt = 0; nt < 4; nt++) {
                    float* d = acc[mt][nt];
                    mma16816(d[0], d[1], d[2], d[3],
                             af[mt][0], af[mt][1], af[mt][2], af[mt][3],
                             bf[nt][0], bf[nt][1]);
                }
        }
        __syncthreads();
    }

    if (FUSE) {
#pragma unroll
        for (int mt = 0; mt < 4; mt++) {
#pragma unroll
            for (int half = 0; half < 2; half++) {
                int row = block_row + warp_m * 64 + mt * 16 + g + half * 8;
                if (row < M) {
                    float s0 = 0.f, s1 = 0.f;
#pragma unroll
                    for (int nt = 0; nt < 4; nt++) {
                        int col = block_col + warp_n * 32 + nt * 8 + 2 * tig;
                        float v0 = acc[mt][nt][half * 2 + 0] + bias[col];
                        float v1 = acc[mt][nt][half * 2 + 1] + bias[col + 1];
                        v0 = leaky(v0); v1 = leaky(v1);
                        s0 += v0 * Wo2[col * 2 + 0] + v1 * Wo2[(col + 1) * 2 + 0];
                        s1 += v0 * Wo2[col * 2 + 1] + v1 * Wo2[(col + 1) * 2 + 1];
                    }
                    s0 += __shfl_xor_sync(0xffffffffu, s0, 1);
                    s0 += __shfl_xor_sync(0xffffffffu, s0, 2);
                    s1 += __shfl_xor_sync(0xffffffffu, s1, 1);
                    s1 += __shfl_xor_sync(0xffffffffu, s1, 2);
                    if (tig == 0) {
                        atomicAdd(&Out[row * 2 + 0], s0);
                        atomicAdd(&Out[row * 2 + 1], s1);
                    }
                }
            }
        }
    } else {
#pragma unroll
        for (int mt = 0; mt < 4; mt++) {
#pragma unroll
            for (int nt = 0; nt < 4; nt++) {
                int row0 = block_row + warp_m * 64 + mt * 16 + g;
                int row1 = row0 + 8;
                int col  = block_col + warp_n * 32 + nt * 8 + 2 * tig;
                float b0 = 0.f, b1 = 0.f;
                if (BIAS_F) { b0 = bias[col]; b1 = bias[col + 1]; }
#pragma unroll
                for (int half = 0; half < 2; half++) {
                    int row = half ? row1 : row0;
                    if (row < M) {
                        float v0 = acc[mt][nt][half * 2 + 0];
                        float v1 = acc[mt][nt][half * 2 + 1];
                        if (BIAS_F)  { v0 += b0; v1 += b1; }
                        if (LEAKY_F) { v0 = leaky(v0); v1 = leaky(v1); }
                        if (SCALE_F) { float dv = g_dinv[row]; v0 *= dv; v1 *= dv; }
                        *(__half2*)(C + (size_t)row * ldc + col) = __floats2half2_rn(v0, v1);
                    }
                }
            }
        }
    }
}

// ---------------- conversions ----------------
__global__ void cvt_f32h(const float* __restrict__ x, __half* __restrict__ o, int n4)
{
    int i = blockIdx.x * blockDim.x + threadIdx.x;
    if (i >= n4) return;
    float4 v = ((const float4*)x)[i];
    uint2 u;
    u.x = packh(__float2half_rn(v.x), __float2half_rn(v.y));
    u.y = packh(__float2half_rn(v.z), __float2half_rn(v.w));
    ((uint2*)o)[i] = u;
}

// W [K, Nn] fp32 -> out [Nn, K] fp16 (transpose)
__global__ void wcvtT(const float* __restrict__ W, int K, int Nn, __half* __restrict__ o)
{
    int idx = blockIdx.x * blockDim.x + threadIdx.x;
    if (idx >= K * Nn) return;
    int k = idx / Nn, n = idx % Nn;
    o[(size_t)n * K + k] = __float2half_rn(W[idx]);
}

// ---------------- small front projections ----------------
__global__ void front_small(const float* __restrict__ nump, const float* __restrict__ catp,
                            const float* __restrict__ Wn, const float* __restrict__ bn,
                            const float* __restrict__ Wc, const float* __restrict__ bc)
{
    int node = blockIdx.x;
    int j = threadIdx.x;
    float n0 = nump[node * 4 + 0], n1 = nump[node * 4 + 1];
    float n2 = nump[node * 4 + 2], n3 = nump[node * 4 + 3];
    float c0 = catp[node * 3 + 0], c1 = catp[node * 3 + 1], c2 = catp[node * 3 + 2];

    float a = bn[j];
    a = fmaf(n0, Wn[0 * 128 + j], a); a = fmaf(n1, Wn[1 * 128 + j], a);
    a = fmaf(n2, Wn[2 * 128 + j], a); a = fmaf(n3, Wn[3 * 128 + j], a);
    float b = bc[j];
    b = fmaf(c0, Wc[0 * 128 + j], b); b = fmaf(c1, Wc[1 * 128 + j], b);
    b = fmaf(c2, Wc[2 * 128 + j], b);

    size_t base = (size_t)node * EMB;
    g_x0[base + 128 + j] = __float2half_rn(leaky(a));
    g_x0[base + 256 + j] = __float2half_rn(leaky(b));
}

// ---------------- edges / CSR ----------------
__device__ __forceinline__ void load_edge(const void* ei, int e, int& src, int& dst) {
    if (g_is64) {
        const long long* p = (const long long*)ei;
        src = (int)p[e]; dst = (int)p[EE + e];
    } else {
        const int* p = (const int*)ei;
        src = p[e]; dst = p[EE + e];
    }
}
__global__ void detect_idx_dtype(const void* ei) {
    const long long* p = (const long long*)ei;
    int ok64 = 1;
    for (int i = 0; i < 64; i++) {
        long long v = p[i];
        if (v < 0 || v >= NN) { ok64 = 0; break; }
    }
    g_is64 = ok64;
}
__global__ void zero_deg() {
    int i = blockIdx.x * blockDim.x + threadIdx.x;
    if (i < NN) g_deg[i] = 0;
}
__global__ void deg_count(const void* __restrict__ ei) {
    int e = blockIdx.x * blockDim.x + threadIdx.x;
    if (e < EE) { int s, d; load_edge(ei, e, s, d); atomicAdd(&g_deg[d], 1); }
}

#define SCAN_BLKS ((NN + 255) / 256)   // 196
__global__ void scan_phase1() {
    __shared__ int ws[8];
    int i = blockIdx.x * 256 + threadIdx.x;
    int lane = threadIdx.x & 31, wd = threadIdx.x >> 5;
    int v = (i < NN) ? g_deg[i] : 0;
    int s = v;
#pragma unroll
    for (int o = 1; o < 32; o <<= 1) {
        int t = __shfl_up_sync(0xffffffffu, s, o);
        if (lane >= o) s += t;
    }
    if (lane == 31) ws[wd] = s;
    __syncthreads();
    if (wd == 0) {
        int u = (lane < 8) ? ws[lane] : 0;
        int ss = u;
#pragma unroll
        for (int o = 1; o < 8; o <<= 1) {
            int t = __shfl_up_sync(0xffffffffu, ss, o);
            if (lane >= o) ss += t;
        }
        if (lane < 8) ws[lane] = ss;
    }
    __syncthreads();
    int incl = s + (wd ? ws[wd - 1] : 0);
    if (i < NN) g_scan[i] = incl;
    if (threadIdx.x == 255) g_bsum[blockIdx.x] = incl;
}
__global__ void scan_phase2() {
    __shared__ int ws[8];
    int t = threadIdx.x;
    int lane = t & 31, wd = t >> 5;
    int v = (t < SCAN_BLKS) ? g_bsum[t] : 0;
    int s = v;
#pragma unroll
    for (int o = 1; o < 32; o <<= 1) {
        int u = __shfl_up_sync(0xffffffffu, s, o);
        if (lane >= o) s += u;
    }
    if (lane == 31) ws[wd] = s;
    __syncthreads();
    if (wd == 0) {
        int u = (lane < 8) ? ws[lane] : 0;
        int ss = u;
#pragma unroll
        for (int o = 1; o < 8; o <<= 1) {
            int x = __shfl_up_sync(0xffffffffu, ss, o);
            if (lane >= o) ss += x;
        }
        if (lane < 8) ws[lane] = ss;
    }
    __syncthreads();
    int incl = s + (wd ? ws[wd - 1] : 0);
    if (t < SCAN_BLKS) g_boff[t] = incl - v;
}
__global__ void scan_phase3() {
    int i = blockIdx.x * 256 + threadIdx.x;
    if (i >= NN) return;
    int incl = g_scan[i] + g_boff[blockIdx.x];
    int d = g_deg[i];
    int beg = incl - d;
    g_rowptr[i] = beg;
    g_cursor[i] = beg;
    g_dinv[i] = rsqrtf((float)d + 1.0f);
    if (i == NN - 1) g_rowptr[NN] = incl;
}

__global__ void csr_fill(const void* __restrict__ ei) {
    int e = blockIdx.x * blockDim.x + threadIdx.x;
    if (e < EE) {
        int s, d; load_edge(ei, e, s, d);
        int pos = atomicAdd(&g_cursor[d], 1);
        g_csr[pos] = s;
    }
}

// ---------------- fused gather-aggregate + combine (single fp16 out) ----------------
__global__ __launch_bounds__(256) void gcn_agg(
    const __half* __restrict__ y, const float* __restrict__ bias,
    __half* __restrict__ ox)
{
    int warp = (blockIdx.x * blockDim.x + threadIdx.x) >> 5;
    int lane = threadIdx.x & 31;
    if (warp >= NN) return;
    int beg = g_rowptr[warp], end = g_rowptr[warp + 1];

    float acc[12];
#pragma unroll
    for (int q = 0; q < 12; q++) acc[q] = 0.0f;

    for (int base = beg; base < end; base += 32) {
        int cnt = min(32, end - base);
        int s = (lane < cnt) ? g_csr[base + lane] : 0;
        for (int j = 0; j < cnt; j++) {
            int sj = __shfl_sync(0xffffffffu, s, j);
            const uint2* ys = (const uint2*)(y + (size_t)sj * EMB);
#pragma unroll
            for (int q = 0; q < 3; q++) {
                uint2 u = ys[lane + q * 32];
                float2 f0 = __half22float2(*(__half2*)&u.x);
                float2 f1 = __half22float2(*(__half2*)&u.y);
                acc[q * 4 + 0] += f0.x; acc[q * 4 + 1] += f0.y;
                acc[q * 4 + 2] += f1.x; acc[q * 4 + 3] += f1.y;
            }
        }
    }
    // self term
    {
        const uint2* yn = (const uint2*)(y + (size_t)warp * EMB);
#pragma unroll
        for (int q = 0; q < 3; q++) {
            uint2 u = yn[lane + q * 32];
            float2 f0 = __half22float2(*(__half2*)&u.x);
            float2 f1 = __half22float2(*(__half2*)&u.y);
            acc[q * 4 + 0] += f0.x; acc[q * 4 + 1] += f0.y;
            acc[q * 4 + 2] += f1.x; acc[q * 4 + 3] += f1.y;
        }
    }

    float dv = g_dinv[warp];
    const float4* bv = (const float4*)bias;
    uint2* oxp = (uint2*)(ox + (size_t)warp * EMB);
#pragma unroll
    for (int q = 0; q < 3; q++) {
        float4 b = bv[lane + q * 32];
        float r0 = fmaf(dv, acc[q * 4 + 0], b.x);
        float r1 = fmaf(dv, acc[q * 4 + 1], b.y);
        float r2 = fmaf(dv, acc[q * 4 + 2], b.z);
        float r3 = fmaf(dv, acc[q * 4 + 3], b.w);
        uint2 u;
        u.x = packh(__float2half_rn(r0), __float2half_rn(r1));
        u.y = packh(__float2half_rn(r2), __float2half_rn(r3));
        oxp[lane + q * 32] = u;
    }
}

// ---------------- output init with bias ----------------
__global__ void init_out(float* __restrict__ out, const float* __restrict__ b) {
    int i = blockIdx.x * blockDim.x + threadIdx.x;
    if (i < NN) {
        out[i * 2 + 0] = b[0];
        out[i * 2 + 1] = b[1];
    }
}

// ---------------- host orchestration ----------------
extern "C" void kernel_launch(void* const* d_in, const int* in_sizes, int n_in,
                              void* d_out, int out_size)
{
    const float* des  = (const float*)d_in[0];
    const float* nump = (const float*)d_in[2];
    const float* catp = (const float*)d_in[3];
    const void*  ei   = d_in[4];
    const float* W_des = (const float*)d_in[5];  const float* b_des = (const float*)d_in[6];
    const float* W_num = (const float*)d_in[7];  const float* b_num = (const float*)d_in[8];
    const float* W_cat = (const float*)d_in[9];  const float* b_cat = (const float*)d_in[10];
    const float* W_in  = (const float*)d_in[11]; const float* b_in  = (const float*)d_in[12];
    const float* W_g1  = (const float*)d_in[13]; const float* b_g1  = (const float*)d_in[14];
    const float* W_g2  = (const float*)d_in[15]; const float* b_g2  = (const float*)d_in[16];
    const float* W_o1  = (const float*)d_in[17]; const float* b_o1  = (const float*)d_in[18];
    const float* W_o2  = (const float*)d_in[19]; const float* b_o2  = (const float*)d_in[20];
    float* out = (float*)d_out;

    __half *h, *desh, *x0, *x1, *w;
    cudaGetSymbolAddress((void**)&h,    g_h);
    cudaGetSymbolAddress((void**)&desh, g_desh);
    cudaGetSymbolAddress((void**)&x0,   g_x0);
    cudaGetSymbolAddress((void**)&x1,   g_x1);
    cudaGetSymbolAddress((void**)&w,    g_w);

    cudaFuncSetAttribute(gemm_hmma<true, true, false, false>,
                         cudaFuncAttributeMaxDynamicSharedMemorySize, GEMM_SMEM);
    cudaFuncSetAttribute(gemm_hmma<false, false, true, false>,
                         cudaFuncAttributeMaxDynamicSharedMemorySize, GEMM_SMEM);
    cudaFuncSetAttribute(gemm_hmma<true, true, false, true>,
                         cudaFuncAttributeMaxDynamicSharedMemorySize, GEMM_SMEM);

    const int MB = (NN + 127) / 128;   // 391
    dim3 blk(256);

    // conversions
    cvt_f32h<<<(NN * DESK / 4 + 255) / 256, blk>>>(des, desh, NN * DESK / 4);
    wcvtT<<<(DESK * 128 + 255) / 256, blk>>>(W_des, DESK, 128, w + WOFF_DES);
    wcvtT<<<(EMB * EMB + 255) / 256, blk>>>(W_in, EMB, EMB, w + WOFF_IN);
    wcvtT<<<(EMB * EMB + 255) / 256, blk>>>(W_g1, EMB, EMB, w + WOFF_G1);
    wcvtT<<<(EMB * EMB + 255) / 256, blk>>>(W_g2, EMB, EMB, w + WOFF_G2);
    wcvtT<<<(EMB * EMB + 255) / 256, blk>>>(W_o1, EMB, EMB, w + WOFF_O1);

    // edge preprocessing
    detect_idx_dtype<<<1, 1>>>(ei);
    zero_deg<<<(NN + 255) / 256, blk>>>();
    deg_count<<<(EE + 255) / 256, blk>>>(ei);
    scan_phase1<<<SCAN_BLKS, 256>>>();
    scan_phase2<<<1, 256>>>();
    scan_phase3<<<SCAN_BLKS, 256>>>();
    csr_fill<<<(EE + 255) / 256, blk>>>(ei);

    // des projection -> x0[:, 0:128]
    gemm_hmma<true, true, false, false><<<dim3(1, MB), blk, GEMM_SMEM>>>(
        desh, DESK, w + WOFF_DES, b_des, x0, EMB, NN, nullptr, nullptr);
    front_small<<<NN, 128>>>(nump, catp, W_num, b_num, W_cat, b_cat);

    // x1 = leaky(x0 @ W_in + b_in)
    gemm_hmma<true, true, false, false><<<dim3(3, MB), blk, GEMM_SMEM>>>(
        x0, EMB, w + WOFF_IN, b_in, x1, EMB, NN, nullptr, nullptr);

    // ---- GCN conv 1 ----
    gemm_hmma<false, false, true, false><<<dim3(3, MB), blk, GEMM_SMEM>>>(
        x1, EMB, w + WOFF_G1, nullptr, h, EMB, NN, nullptr, nullptr);
    gcn_agg<<<(NN * 32 + 255) / 256, blk>>>(h, b_g1, x1);

    // ---- GCN conv 2 ----
    gemm_hmma<false, false, true, false><<<dim3(3, MB), blk, GEMM_SMEM>>>(
        x1, EMB, w + WOFF_G2, nullptr, h, EMB, NN, nullptr, nullptr);
    gcn_agg<<<(NN * 32 + 255) / 256, blk>>>(h, b_g2, x1);

    // fused: out = leaky(x @ W_o1 + b_o1) @ W_o2 + b_o2
    init_out<<<(NN + 255) / 256, blk>>>(out, b_o2);
    gemm_hmma<true, true, false, true><<<dim3(3, MB), blk, GEMM_SMEM>>>(
        x1, EMB, w + WOFF_O1, b_o1, nullptr, EMB, NN, W_o2, out);
}

// round 16
// speedup vs baseline: 1.4614x; 1.0187x over previous
#include <cuda_runtime.h>
#include <cuda_fp16.h>
#include <stdint.h>

#define NN   50000
#define EE   800000
#define EMB  384
#define DESK 768

// ---------------- scratch (no allocations allowed) ----------------
__device__ __align__(16) __half g_h[NN * EMB];      // fp16 message rows
__device__ float g_dinv[NN];
__device__ int   g_deg[NN];
__device__ int   g_rowptr[NN + 1];
__device__ int   g_cursor[NN];
__device__ int   g_csr[EE];
__device__ int   g_scan[NN];
__device__ int   g_bsum[256];
__device__ int   g_boff[256];
__device__ int   g_is64;

__device__ __align__(16) __half g_desh[NN * DESK];   // des fp16
__device__ __align__(16) __half g_x0[NN * EMB];      // activations: single fp16
__device__ __align__(16) __half g_x1[NN * EMB];

#define WTOT 688128
__device__ __align__(16) __half g_w[WTOT];
enum { WOFF_DES = 0, WOFF_IN = 98304, WOFF_G1 = 245760, WOFF_G2 = 393216, WOFF_O1 = 540672 };

__device__ __forceinline__ float leaky(float v) { return v > 0.0f ? v : 0.01f * v; }
__device__ __forceinline__ uint32_t packh(__half a, __half b) {
    __half2 t = __halves2half2(a, b);
    return *(uint32_t*)&t;
}

// ---------------- low-level helpers ----------------
__device__ __forceinline__ uint32_t smem_u32(const void* p) {
    uint32_t a;
    asm("{ .reg .u64 t; cvta.to.shared.u64 t, %1; cvt.u32.u64 %0, t; }" : "=r"(a) : "l"(p));
    return a;
}
__device__ __forceinline__ void cp_async16(uint32_t dst, const void* src) {
    asm volatile("cp.async.cg.shared.global [%0], [%1], 16;" :: "r"(dst), "l"(src));
}
__device__ __forceinline__ void cp_commit() { asm volatile("cp.async.commit_group;" ::: "memory"); }
__device__ __forceinline__ void cp_wait_all() { asm volatile("cp.async.wait_group 0;" ::: "memory"); }
__device__ __forceinline__ void cp_wait_1()  { asm volatile("cp.async.wait_group 1;" ::: "memory"); }

__device__ __forceinline__ void mma16816(float& d0, float& d1, float& d2, float& d3,
                                         uint32_t a0, uint32_t a1, uint32_t a2, uint32_t a3,
                                         uint32_t b0, uint32_t b1)
{
    asm volatile(
        "mma.sync.aligned.m16n8k16.row.col.f32.f16.f16.f32 "
        "{%0,%1,%2,%3}, {%4,%5,%6,%7}, {%8,%9}, {%0,%1,%2,%3};"
        : "+f"(d0), "+f"(d1), "+f"(d2), "+f"(d3)
        : "r"(a0), "r"(a1), "r"(a2), "r"(a3), "r"(b0), "r"(b1));
}
__device__ __forceinline__ void ldsm4(uint32_t& r0, uint32_t& r1, uint32_t& r2, uint32_t& r3,
                                      uint32_t addr)
{
    asm volatile("ldmatrix.sync.aligned.m8n8.x4.shared.b16 {%0,%1,%2,%3}, [%4];"
                 : "=r"(r0), "=r"(r1), "=r"(r2), "=r"(r3) : "r"(addr));
}

// ---------------- single-fp16 HMMA GEMM: D = A @ B^T ----------------
#define ROW_PITCH 80
#define TILE_B    (128 * ROW_PITCH)      // 10240
#define STAGE     (2 * TILE_B)           // 20480
#define GEMM_SMEM (2 * STAGE)            // 40960

template<bool LEAKY_F, bool BIAS_F, bool SCALE_F, bool FUSE>
__global__ __launch_bounds__(256) void gemm_hmma(
    const __half* __restrict__ A, int K,
    const __half* __restrict__ B,
    const float* __restrict__ bias,
    __half* __restrict__ C, int ldc, int M,
    const float* __restrict__ Wo2, float* __restrict__ Out)
{
    extern __shared__ char smem[];
    const uint32_t sb = smem_u32(smem);
    const int tid  = threadIdx.x;
    const int wid  = tid >> 5;
    const int lane = tid & 31;
    const int g    = lane >> 2;
    const int tig  = lane & 3;
    const int warp_m = wid >> 2;
    const int warp_n = wid & 3;
    const int block_row = blockIdx.y * 128;
    const int block_col = blockIdx.x * 128;

    float acc[4][4][4];
#pragma unroll
    for (int mt = 0; mt < 4; mt++)
#pragma unroll
        for (int nt = 0; nt < 4; nt++)
#pragma unroll
            for (int q = 0; q < 4; q++) acc[mt][nt][q] = 0.0f;

    const int NC = K >> 5;

    auto load_stage = [&](int c, int s) {
        const uint32_t stage = sb + s * STAGE;
        const int kbyte = c * 64;
#pragma unroll
        for (int i = 0; i < 4; i++) {
            int gi   = tid + i * 256;
            int tile = gi >> 9;
            int r    = (gi >> 2) & 127;
            int c16  = gi & 3;
            int grow;
            if (tile == 0) { grow = block_row + r; if (grow >= M) grow = M - 1; }
            else           { grow = block_col + r; }
            const __half* base = tile ? B : A;
            const char* src = (const char*)base + (size_t)grow * K * 2 + kbyte + c16 * 16;
            cp_async16(stage + tile * TILE_B + r * ROW_PITCH + c16 * 16, src);
        }
        cp_commit();
    };

    const uint32_t aOff = (uint32_t)(warp_m * 64 + (lane & 15)) * ROW_PITCH + (lane >> 4) * 16;
    const uint32_t bOff = TILE_B
                        + (uint32_t)(warp_n * 32 + (lane & 7) + ((lane >> 4) * 8)) * ROW_PITCH
                        + ((lane >> 3) & 1) * 16;

    load_stage(0, 0);

    for (int c = 0; c < NC; c++) {
        if (c + 1 < NC) { load_stage(c + 1, (c + 1) & 1); cp_wait_1(); }
        else            { cp_wait_all(); }
        __syncthreads();

        const uint32_t stage = sb + (c & 1) * STAGE;
        const uint32_t aBase = stage + aOff;
        const uint32_t bBase = stage + bOff;

#pragma unroll
        for (int kk = 0; kk < 32; kk += 16) {
            const uint32_t ko = kk * 2;
            uint32_t af[4][4];
#pragma unroll
            for (int mt = 0; mt < 4; mt++)
                ldsm4(af[mt][0], af[mt][1], af[mt][2], af[mt][3],
                      aBase + mt * (16 * ROW_PITCH) + ko);

            uint32_t bf[4][2];
#pragma unroll
            for (int p = 0; p < 2; p++)
                ldsm4(bf[2 * p][0], bf[2 * p][1], bf[2 * p + 1][0], bf[2 * p + 1][1],
                      bBase + p * (16 * ROW_PITCH) + ko);

#pragma unroll
            for (int mt = 0; mt < 4; mt++)
#pragma unroll
                for (int nt = 0; nt < 4; nt++) {
                    float* d = acc[mt][nt];
                    mma16816(d[0], d[1], d[2], d[3],
                             af[mt][0], af[mt][1], af[mt][2], af[mt][3],
                             bf[nt][0], bf[nt][1]);
                }
        }
        __syncthreads();
    }

    if (FUSE) {
#pragma unroll
        for (int mt = 0; mt < 4; mt++) {
#pragma unroll
            for (int half = 0; half < 2; half++) {
                int row = block_row + warp_m * 64 + mt * 16 + g + half * 8;
                if (row < M) {
                    float s0 = 0.f, s1 = 0.f;
#pragma unroll
                    for (int nt = 0; nt < 4; nt++) {
                        int col = block_col + warp_n * 32 + nt * 8 + 2 * tig;
                        float v0 = acc[mt][nt][half * 2 + 0] + bias[col];
                        float v1 = acc[mt][nt][half * 2 + 1] + bias[col + 1];
                        v0 = leaky(v0); v1 = leaky(v1);
                        s0 += v0 * Wo2[col * 2 + 0] + v1 * Wo2[(col + 1) * 2 + 0];
                        s1 += v0 * Wo2[col * 2 + 1] + v1 * Wo2[(col + 1) * 2 + 1];
                    }
                    s0 += __shfl_xor_sync(0xffffffffu, s0, 1);
                    s0 += __shfl_xor_sync(0xffffffffu, s0, 2);
                    s1 += __shfl_xor_sync(0xffffffffu, s1, 1);
                    s1 += __shfl_xor_sync(0xffffffffu, s1, 2);
                    if (tig == 0) {
                        atomicAdd(&Out[row * 2 + 0], s0);
                        atomicAdd(&Out[row * 2 + 1], s1);
                    }
                }
            }
        }
    } else {
#pragma unroll
        for (int mt = 0; mt < 4; mt++) {
#pragma unroll
            for (int nt = 0; nt < 4; nt++) {
                int row0 = block_row + warp_m * 64 + mt * 16 + g;
                int row1 = row0 + 8;
                int col  = block_col + warp_n * 32 + nt * 8 + 2 * tig;
                float b0 = 0.f, b1 = 0.f;
                if (BIAS_F) { b0 = bias[col]; b1 = bias[col + 1]; }
#pragma unroll
                for (int half = 0; half < 2; half++) {
                    int row = half ? row1 : row0;
                    if (row < M) {
                        float v0 = acc[mt][nt][half * 2 + 0];
                        float v1 = acc[mt][nt][half * 2 + 1];
                        if (BIAS_F)  { v0 += b0; v1 += b1; }
                        if (LEAKY_F) { v0 = leaky(v0); v1 = leaky(v1); }
                        if (SCALE_F) { float dv = g_dinv[row]; v0 *= dv; v1 *= dv; }
                        *(__half2*)(C + (size_t)row * ldc + col) = __floats2half2_rn(v0, v1);
                    }
                }
            }
        }
    }
}

// ---------------- conversions ----------------
__global__ void cvt_f32h(const float* __restrict__ x, __half* __restrict__ o, int n4)
{
    int i = blockIdx.x * blockDim.x + threadIdx.x;
    if (i >= n4) return;
    float4 v = ((const float4*)x)[i];
    uint2 u;
    u.x = packh(__float2half_rn(v.x), __float2half_rn(v.y));
    u.y = packh(__float2half_rn(v.z), __float2half_rn(v.w));
    ((uint2*)o)[i] = u;
}

__global__ void wcvtT(const float* __restrict__ W, int K, int Nn, __half* __restrict__ o)
{
    int idx = blockIdx.x * blockDim.x + threadIdx.x;
    if (idx >= K * Nn) return;
    int k = idx / Nn, n = idx % Nn;
    o[(size_t)n * K + k] = __float2half_rn(W[idx]);
}

// ---------------- small front projections ----------------
__global__ void front_small(const float* __restrict__ nump, const float* __restrict__ catp,
                            const float* __restrict__ Wn, const float* __restrict__ bn,
                            const float* __restrict__ Wc, const float* __restrict__ bc)
{
    int node = blockIdx.x;
    int j = threadIdx.x;
    float n0 = nump[node * 4 + 0], n1 = nump[node * 4 + 1];
    float n2 = nump[node * 4 + 2], n3 = nump[node * 4 + 3];
    float c0 = catp[node * 3 + 0], c1 = catp[node * 3 + 1], c2 = catp[node * 3 + 2];

    float a = bn[j];
    a = fmaf(n0, Wn[0 * 128 + j], a); a = fmaf(n1, Wn[1 * 128 + j], a);
    a = fmaf(n2, Wn[2 * 128 + j], a); a = fmaf(n3, Wn[3 * 128 + j], a);
    float b = bc[j];
    b = fmaf(c0, Wc[0 * 128 + j], b); b = fmaf(c1, Wc[1 * 128 + j], b);
    b = fmaf(c2, Wc[2 * 128 + j], b);

    size_t base = (size_t)node * EMB;
    g_x0[base + 128 + j] = __float2half_rn(leaky(a));
    g_x0[base + 256 + j] = __float2half_rn(leaky(b));
}

// ---------------- edges / CSR ----------------
__device__ __forceinline__ void load_edge(const void* ei, int e, int& src, int& dst) {
    if (g_is64) {
        const long long* p = (const long long*)ei;
        src = (int)p[e]; dst = (int)p[EE + e];
    } else {
        const int* p = (const int*)ei;
        src = p[e]; dst = p[EE + e];
    }
}
__global__ void detect_idx_dtype(const void* ei) {
    const long long* p = (const long long*)ei;
    int ok64 = 1;
    for (int i = 0; i < 64; i++) {
        long long v = p[i];
        if (v < 0 || v >= NN) { ok64 = 0; break; }
    }
    g_is64 = ok64;
}
__global__ void zero_deg() {
    int i = blockIdx.x * blockDim.x + threadIdx.x;
    if (i < NN) g_deg[i] = 0;
}
__global__ void deg_count(const void* __restrict__ ei) {
    int e = blockIdx.x * blockDim.x + threadIdx.x;
    if (e < EE) { int s, d; load_edge(ei, e, s, d); atomicAdd(&g_deg[d], 1); }
}

#define SCAN_BLKS ((NN + 255) / 256)   // 196
__global__ void scan_phase1() {
    __shared__ int ws[8];
    int i = blockIdx.x * 256 + threadIdx.x;
    int lane = threadIdx.x & 31, wd = threadIdx.x >> 5;
    int v = (i < NN) ? g_deg[i] : 0;
    int s = v;
#pragma unroll
    for (int o = 1; o < 32; o <<= 1) {
        int t = __shfl_up_sync(0xffffffffu, s, o);
        if (lane >= o) s += t;
    }
    if (lane == 31) ws[wd] = s;
    __syncthreads();
    if (wd == 0) {
        int u = (lane < 8) ? ws[lane] : 0;
        int ss = u;
#pragma unroll
        for (int o = 1; o < 8; o <<= 1) {
            int t = __shfl_up_sync(0xffffffffu, ss, o);
            if (lane >= o) ss += t;
        }
        if (lane < 8) ws[lane] = ss;
    }
    __syncthreads();
    int incl = s + (wd ? ws[wd - 1] : 0);
    if (i < NN) g_scan[i] = incl;
    if (threadIdx.x == 255) g_bsum[blockIdx.x] = incl;
}
__global__ void scan_phase2() {
    __shared__ int ws[8];
    int t = threadIdx.x;
    int lane = t & 31, wd = t >> 5;
    int v = (t < SCAN_BLKS) ? g_bsum[t] : 0;
    int s = v;
#pragma unroll
    for (int o = 1; o < 32; o <<= 1) {
        int u = __shfl_up_sync(0xffffffffu, s, o);
        if (lane >= o) s += u;
    }
    if (lane == 31) ws[wd] = s;
    __syncthreads();
    if (wd == 0) {
        int u = (lane < 8) ? ws[lane] : 0;
        int ss = u;
#pragma unroll
        for (int o = 1; o < 8; o <<= 1) {
            int x = __shfl_up_sync(0xffffffffu, ss, o);
            if (lane >= o) ss += x;
        }
        if (lane < 8) ws[lane] = ss;
    }
    __syncthreads();
    int incl = s + (wd ? ws[wd - 1] : 0);
    if (t < SCAN_BLKS) g_boff[t] = incl - v;
}
__global__ void scan_phase3() {
    int i = blockIdx.x * 256 + threadIdx.x;
    if (i >= NN) return;
    int incl = g_scan[i] + g_boff[blockIdx.x];
    int d = g_deg[i];
    int beg = incl - d;
    g_rowptr[i] = beg;
    g_cursor[i] = beg;
    g_dinv[i] = rsqrtf((float)d + 1.0f);
    if (i == NN - 1) g_rowptr[NN] = incl;
}

__global__ void csr_fill(const void* __restrict__ ei) {
    int e = blockIdx.x * blockDim.x + threadIdx.x;
    if (e < EE) {
        int s, d; load_edge(ei, e, s, d);
        int pos = atomicAdd(&g_cursor[d], 1);
        g_csr[pos] = s;
    }
}

// ---------------- fused gather-aggregate + combine (single fp16 out) ----------------
__global__ __launch_bounds__(256) void gcn_agg(
    const __half* __restrict__ y, const float* __restrict__ bias,
    __half* __restrict__ ox)
{
    int warp = (blockIdx.x * blockDim.x + threadIdx.x) >> 5;
    int lane = threadIdx.x & 31;
    if (warp >= NN) return;
    int beg = g_rowptr[warp], end = g_rowptr[warp + 1];

    float acc[12];
#pragma unroll
    for (int q = 0; q < 12; q++) acc[q] = 0.0f;

    for (int base = beg; base < end; base += 32) {
        int cnt = min(32, end - base);
        int s = (lane < cnt) ? g_csr[base + lane] : 0;
        for (int j = 0; j < cnt; j++) {
            int sj = __shfl_sync(0xffffffffu, s, j);
            const uint2* ys = (const uint2*)(y + (size_t)sj * EMB);
#pragma unroll
            for (int q = 0; q < 3; q++) {
                uint2 u = ys[lane + q * 32];
                float2 f0 = __half22float2(*(__half2*)&u.x);
                float2 f1 = __half22float2(*(__half2*)&u.y);
                acc[q * 4 + 0] += f0.x; acc[q * 4 + 1] += f0.y;
                acc[q * 4 + 2] += f1.x; acc[q * 4 + 3] += f1.y;
            }
        }
    }
    // self term
    {
        const uint2* yn = (const uint2*)(y + (size_t)warp * EMB);
#pragma unroll
        for (int q = 0; q < 3; q++) {
            uint2 u = yn[lane + q * 32];
            float2 f0 = __half22float2(*(__half2*)&u.x);
            float2 f1 = __half22float2(*(__half2*)&u.y);
            acc[q * 4 + 0] += f0.x; acc[q * 4 + 1] += f0.y;
            acc[q * 4 + 2] += f1.x; acc[q * 4 + 3] += f1.y;
        }
    }

    float dv = g_dinv[warp];
    const float4* bv = (const float4*)bias;
    uint2* oxp = (uint2*)(ox + (size_t)warp * EMB);
#pragma unroll
    for (int q = 0; q < 3; q++) {
        float4 b = bv[lane + q * 32];
        float r0 = fmaf(dv, acc[q * 4 + 0], b.x);
        float r1 = fmaf(dv, acc[q * 4 + 1], b.y);
        float r2 = fmaf(dv, acc[q * 4 + 2], b.z);
        float r3 = fmaf(dv, acc[q * 4 + 3], b.w);
        uint2 u;
        u.x = packh(__float2half_rn(r0), __float2half_rn(r1));
        u.y = packh(__float2half_rn(r2), __float2half_rn(r3));
        oxp[lane + q * 32] = u;
    }
}

// ---------------- output init with bias ----------------
__global__ void init_out(float* __restrict__ out, const float* __restrict__ b) {
    int i = blockIdx.x * blockDim.x + threadIdx.x;
    if (i < NN) {
        out[i * 2 + 0] = b[0];
        out[i * 2 + 1] = b[1];
    }
}

// ---------------- host orchestration (fork/join graph) ----------------
extern "C" void kernel_launch(void* const* d_in, const int* in_sizes, int n_in,
                              void* d_out, int out_size)
{
    const float* des  = (const float*)d_in[0];
    const float* nump = (const float*)d_in[2];
    const float* catp = (const float*)d_in[3];
    const void*  ei   = d_in[4];
    const float* W_des = (const float*)d_in[5];  const float* b_des = (const float*)d_in[6];
    const float* W_num = (const float*)d_in[7];  const float* b_num = (const float*)d_in[8];
    const float* W_cat = (const float*)d_in[9];  const float* b_cat = (const float*)d_in[10];
    const float* W_in  = (const float*)d_in[11]; const float* b_in  = (const float*)d_in[12];
    const float* W_g1  = (const float*)d_in[13]; const float* b_g1  = (const float*)d_in[14];
    const float* W_g2  = (const float*)d_in[15]; const float* b_g2  = (const float*)d_in[16];
    const float* W_o1  = (const float*)d_in[17]; const float* b_o1  = (const float*)d_in[18];
    const float* W_o2  = (const float*)d_in[19]; const float* b_o2  = (const float*)d_in[20];
    float* out = (float*)d_out;

    __half *h, *desh, *x0, *x1, *w;
    cudaGetSymbolAddress((void**)&h,    g_h);
    cudaGetSymbolAddress((void**)&desh, g_desh);
    cudaGetSymbolAddress((void**)&x0,   g_x0);
    cudaGetSymbolAddress((void**)&x1,   g_x1);
    cudaGetSymbolAddress((void**)&w,    g_w);

    cudaFuncSetAttribute(gemm_hmma<true, true, false, false>,
                         cudaFuncAttributeMaxDynamicSharedMemorySize, GEMM_SMEM);
    cudaFuncSetAttribute(gemm_hmma<false, false, true, false>,
                         cudaFuncAttributeMaxDynamicSharedMemorySize, GEMM_SMEM);
    cudaFuncSetAttribute(gemm_hmma<true, true, false, true>,
                         cudaFuncAttributeMaxDynamicSharedMemorySize, GEMM_SMEM);

    const int MB = (NN + 127) / 128;   // 391
    dim3 blk(256);

    // fork a side stream for the edge-preprocessing chain (host objects only;
    // deferred destruction, no device allocations)
    cudaStream_t s2;
    cudaStreamCreate(&s2);
    cudaEvent_t e0, e1;
    cudaEventCreate(&e0);
    cudaEventCreate(&e1);

    // fork point: s2 inherits capture from the main (default) stream
    cudaEventRecord(e0, 0);
    cudaStreamWaitEvent(s2, e0, 0);

    // ---- branch A (s2): edge preprocessing ----
    detect_idx_dtype<<<1, 1, 0, s2>>>(ei);
    zero_deg<<<(NN + 255) / 256, blk, 0, s2>>>();
    deg_count<<<(EE + 255) / 256, blk, 0, s2>>>(ei);
    scan_phase1<<<SCAN_BLKS, 256, 0, s2>>>();
    scan_phase2<<<1, 256, 0, s2>>>();
    scan_phase3<<<SCAN_BLKS, 256, 0, s2>>>();
    csr_fill<<<(EE + 255) / 256, blk, 0, s2>>>(ei);
    cudaEventRecord(e1, s2);

    // ---- branch B (default stream): feature front-end ----
    cvt_f32h<<<(NN * DESK / 4 + 255) / 256, blk>>>(des, desh, NN * DESK / 4);
    wcvtT<<<(DESK * 128 + 255) / 256, blk>>>(W_des, DESK, 128, w + WOFF_DES);
    wcvtT<<<(EMB * EMB + 255) / 256, blk>>>(W_in, EMB, EMB, w + WOFF_IN);
    wcvtT<<<(EMB * EMB + 255) / 256, blk>>>(W_g1, EMB, EMB, w + WOFF_G1);
    wcvtT<<<(EMB * EMB + 255) / 256, blk>>>(W_g2, EMB, EMB, w + WOFF_G2);
    wcvtT<<<(EMB * EMB + 255) / 256, blk>>>(W_o1, EMB, EMB, w + WOFF_O1);

    // des projection -> x0[:, 0:128]
    gemm_hmma<true, true, false, false><<<dim3(1, MB), blk, GEMM_SMEM>>>(
        desh, DESK, w + WOFF_DES, b_des, x0, EMB, NN, nullptr, nullptr);
    front_small<<<NN, 128>>>(nump, catp, W_num, b_num, W_cat, b_cat);

    // x1 = leaky(x0 @ W_in + b_in)
    gemm_hmma<true, true, false, false><<<dim3(3, MB), blk, GEMM_SMEM>>>(
        x0, EMB, w + WOFF_IN, b_in, x1, EMB, NN, nullptr, nullptr);

    // join: conv-1 needs dinv + CSR from branch A
    cudaStreamWaitEvent(0, e1, 0);

    // ---- GCN conv 1 ----
    gemm_hmma<false, false, true, false><<<dim3(3, MB), blk, GEMM_SMEM>>>(
        x1, EMB, w + WOFF_G1, nullptr, h, EMB, NN, nullptr, nullptr);
    gcn_agg<<<(NN * 32 + 255) / 256, blk>>>(h, b_g1, x1);

    // ---- GCN conv 2 ----
    gemm_hmma<false, false, true, false><<<dim3(3, MB), blk, GEMM_SMEM>>>(
        x1, EMB, w + WOFF_G2, nullptr, h, EMB, NN, nullptr, nullptr);
    gcn_agg<<<(NN * 32 + 255) / 256, blk>>>(h, b_g2, x1);

    // fused: out = leaky(x @ W_o1 + b_o1) @ W_o2 + b_o2
    init_out<<<(NN + 255) / 256, blk>>>(out, b_o2);
    gemm_hmma<true, true, false, true><<<dim3(3, MB), blk, GEMM_SMEM>>>(
        x1, EMB, w + WOFF_O1, b_o1, nullptr, EMB, NN, W_o2, out);

    // host-object cleanup (deferred by the driver; nothing device-allocated)
    cudaEventDestroy(e0);
    cudaEventDestroy(e1);
    cudaStreamDestroy(s2);
}